// round 1
// baseline (speedup 1.0000x reference)
#include <cuda_runtime.h>
#include <math.h>

#define D_MODEL 1024
#define N_HEADS 16
#define D_HEAD  64
#define BATCH   4
#define SEQ     2048
#define M_ROWS  (BATCH * SEQ)   // 8192

// ---------------- scratch (device globals; no allocation) ----------------
__device__ float g_Xn[M_ROWS * D_MODEL];
__device__ float g_Q [M_ROWS * D_MODEL];
__device__ float g_K [M_ROWS * D_MODEL];
__device__ float g_V [M_ROWS * D_MODEL];
__device__ float g_O [M_ROWS * D_MODEL];

// ---------------- LayerNorm ----------------
// grid = M_ROWS, block = 256. Each thread handles one float4 (1024/256 = 4 floats).
__global__ __launch_bounds__(256) void ln_kernel(
    const float* __restrict__ X, const float* __restrict__ gamma,
    const float* __restrict__ beta, float* __restrict__ Xn)
{
    int row = blockIdx.x;
    int tid = threadIdx.x;
    const float4* xr = reinterpret_cast<const float4*>(X + (size_t)row * D_MODEL);
    float4 v = xr[tid];

    float s  = v.x + v.y + v.z + v.w;
    float sq = v.x*v.x + v.y*v.y + v.z*v.z + v.w*v.w;

    // warp reduce
    #pragma unroll
    for (int o = 16; o > 0; o >>= 1) {
        s  += __shfl_xor_sync(0xffffffffu, s,  o);
        sq += __shfl_xor_sync(0xffffffffu, sq, o);
    }
    __shared__ float ss[8], ssq[8];
    int wid = tid >> 5, lid = tid & 31;
    if (lid == 0) { ss[wid] = s; ssq[wid] = sq; }
    __syncthreads();
    if (wid == 0) {
        float a = (lid < 8) ? ss[lid]  : 0.f;
        float b = (lid < 8) ? ssq[lid] : 0.f;
        #pragma unroll
        for (int o = 4; o > 0; o >>= 1) {
            a += __shfl_xor_sync(0xffffffffu, a, o);
            b += __shfl_xor_sync(0xffffffffu, b, o);
        }
        if (lid == 0) { ss[0] = a; ssq[0] = b; }
    }
    __syncthreads();
    float mean = ss[0] * (1.0f / D_MODEL);
    float var  = ssq[0] * (1.0f / D_MODEL) - mean * mean;
    float rstd = rsqrtf(var + 1e-5f);

    const float4* g4 = reinterpret_cast<const float4*>(gamma);
    const float4* b4 = reinterpret_cast<const float4*>(beta);
    float4 gv = g4[tid], bv = b4[tid];
    float4 o;
    o.x = (v.x - mean) * rstd * gv.x + bv.x;
    o.y = (v.y - mean) * rstd * gv.y + bv.y;
    o.z = (v.z - mean) * rstd * gv.z + bv.z;
    o.w = (v.w - mean) * rstd * gv.w + bv.w;
    reinterpret_cast<float4*>(Xn + (size_t)row * D_MODEL)[tid] = o;
}

// ---------------- SGEMM: C[M,N] = A[M,K] @ W[N,K]^T + bias[N] ----------------
// BM=BN=128, BK=16, 256 threads, each thread 8x8.
#define BM 128
#define BN 128
#define BK 16
#define TM 8
#define TN 8

__global__ __launch_bounds__(256) void gemm_nt_bias(
    const float* __restrict__ A, const float* __restrict__ W,
    const float* __restrict__ bias, float* __restrict__ C,
    int M, int N, int K)
{
    __shared__ float As[BK][BM];
    __shared__ float Bs[BK][BN];

    int tid = threadIdx.x;
    int bm = blockIdx.y * BM;
    int bn = blockIdx.x * BN;

    int lrow = tid >> 2;       // 0..63
    int lc4  = tid & 3;        // 0..3 (float4 index within BK=16 floats)

    int tx = tid & 15;         // col group
    int ty = tid >> 4;         // row group
    int tm = ty * TM;
    int tn = tx * TN;

    float acc[TM][TN];
    #pragma unroll
    for (int i = 0; i < TM; i++)
        #pragma unroll
        for (int j = 0; j < TN; j++) acc[i][j] = 0.f;

    for (int kt = 0; kt < K; kt += BK) {
        // load A tile (128 x 16) transposed into As[k][m]
        #pragma unroll
        for (int r = 0; r < 2; r++) {
            int arow = lrow + r * 64;
            float4 a = *reinterpret_cast<const float4*>(
                A + (size_t)(bm + arow) * K + kt + lc4 * 4);
            As[lc4*4+0][arow] = a.x;
            As[lc4*4+1][arow] = a.y;
            As[lc4*4+2][arow] = a.z;
            As[lc4*4+3][arow] = a.w;
            float4 b = *reinterpret_cast<const float4*>(
                W + (size_t)(bn + arow) * K + kt + lc4 * 4);
            Bs[lc4*4+0][arow] = b.x;
            Bs[lc4*4+1][arow] = b.y;
            Bs[lc4*4+2][arow] = b.z;
            Bs[lc4*4+3][arow] = b.w;
        }
        __syncthreads();

        #pragma unroll
        for (int kk = 0; kk < BK; kk++) {
            float ra[TM], rb[TN];
            #pragma unroll
            for (int i = 0; i < TM; i++) ra[i] = As[kk][tm + i];
            #pragma unroll
            for (int j = 0; j < TN; j++) rb[j] = Bs[kk][tn + j];
            #pragma unroll
            for (int i = 0; i < TM; i++)
                #pragma unroll
                for (int j = 0; j < TN; j++)
                    acc[i][j] += ra[i] * rb[j];
        }
        __syncthreads();
    }

    #pragma unroll
    for (int i = 0; i < TM; i++) {
        float* crow = C + (size_t)(bm + tm + i) * N + bn + tn;
        #pragma unroll
        for (int j = 0; j < TN; j += 4) {
            float4 o;
            o.x = acc[i][j+0] + bias[bn + tn + j + 0];
            o.y = acc[i][j+1] + bias[bn + tn + j + 1];
            o.z = acc[i][j+2] + bias[bn + tn + j + 2];
            o.w = acc[i][j+3] + bias[bn + tn + j + 3];
            *reinterpret_cast<float4*>(crow + j) = o;
        }
    }
}

// ---------------- Causal flash attention (fp32, online softmax) ----------------
// grid = (S/64, H, B), block = 64 threads; each thread owns one query row.
#define BR 64
#define BC 32

__global__ __launch_bounds__(64) void attn_kernel(
    const float* __restrict__ Q, const float* __restrict__ K,
    const float* __restrict__ V, float* __restrict__ O)
{
    int qt = blockIdx.x;
    int h  = blockIdx.y;
    int b  = blockIdx.z;
    int row = qt * BR + threadIdx.x;          // query position within sequence

    const float scale = 0.125f;               // 1/sqrt(64)

    __shared__ float Ks[BC][D_HEAD];
    __shared__ float Vs[BC][D_HEAD];

    // load q into registers, pre-scaled
    float q[D_HEAD];
    {
        const float4* qp = reinterpret_cast<const float4*>(
            Q + ((size_t)(b * SEQ + row)) * D_MODEL + h * D_HEAD);
        #pragma unroll
        for (int c = 0; c < 16; c++) {
            float4 v = qp[c];
            q[c*4+0] = v.x * scale; q[c*4+1] = v.y * scale;
            q[c*4+2] = v.z * scale; q[c*4+3] = v.w * scale;
        }
    }

    float acc[D_HEAD];
    #pragma unroll
    for (int d = 0; d < D_HEAD; d++) acc[d] = 0.f;
    float m = -INFINITY, l = 0.f;

    int kend = qt * BR + BR;                   // max causal reach for this block

    for (int kbase = 0; kbase < kend; kbase += BC) {
        __syncthreads();
        // cooperative load of K/V tile (BC x 64), float4-coalesced
        for (int i = threadIdx.x; i < BC * 16; i += 64) {
            int j  = i >> 4;
            int c  = i & 15;
            size_t goff = ((size_t)(b * SEQ + kbase + j)) * D_MODEL + h * D_HEAD + c * 4;
            reinterpret_cast<float4*>(Ks[j])[c] =
                *reinterpret_cast<const float4*>(K + goff);
            reinterpret_cast<float4*>(Vs[j])[c] =
                *reinterpret_cast<const float4*>(V + goff);
        }
        __syncthreads();

        int jmax = row + 1 - kbase;
        if (jmax > BC) jmax = BC;
        for (int j = 0; j < jmax; j++) {
            const float4* kr = reinterpret_cast<const float4*>(Ks[j]);
            float s = 0.f;
            #pragma unroll
            for (int c = 0; c < 16; c++) {
                float4 k4 = kr[c];
                s += q[c*4+0]*k4.x + q[c*4+1]*k4.y + q[c*4+2]*k4.z + q[c*4+3]*k4.w;
            }
            if (s > m) {
                float corr = __expf(m - s);   // m=-inf -> 0, safe
                l *= corr;
                #pragma unroll
                for (int d = 0; d < D_HEAD; d++) acc[d] *= corr;
                m = s;
            }
            float p = __expf(s - m);
            l += p;
            const float4* vr = reinterpret_cast<const float4*>(Vs[j]);
            #pragma unroll
            for (int c = 0; c < 16; c++) {
                float4 v4 = vr[c];
                acc[c*4+0] += p * v4.x; acc[c*4+1] += p * v4.y;
                acc[c*4+2] += p * v4.z; acc[c*4+3] += p * v4.w;
            }
        }
    }

    float inv = 1.f / l;
    float4* op = reinterpret_cast<float4*>(
        O + ((size_t)(b * SEQ + row)) * D_MODEL + h * D_HEAD);
    #pragma unroll
    for (int c = 0; c < 16; c++) {
        float4 o;
        o.x = acc[c*4+0] * inv; o.y = acc[c*4+1] * inv;
        o.z = acc[c*4+2] * inv; o.w = acc[c*4+3] * inv;
        op[c] = o;
    }
}

// ---------------- launch ----------------
extern "C" void kernel_launch(void* const* d_in, const int* in_sizes, int n_in,
                              void* d_out, int out_size)
{
    const float* X        = (const float*)d_in[0];
    const float* ln_gamma = (const float*)d_in[1];
    const float* ln_beta  = (const float*)d_in[2];
    const float* Wq       = (const float*)d_in[3];
    const float* bq       = (const float*)d_in[4];
    const float* Wk       = (const float*)d_in[5];
    const float* bk       = (const float*)d_in[6];
    const float* Wv       = (const float*)d_in[7];
    const float* bv       = (const float*)d_in[8];
    const float* Wo       = (const float*)d_in[9];
    const float* bo       = (const float*)d_in[10];
    float* out = (float*)d_out;

    float *Xn, *Qm, *Km, *Vm, *Om;
    cudaGetSymbolAddress((void**)&Xn, g_Xn);
    cudaGetSymbolAddress((void**)&Qm, g_Q);
    cudaGetSymbolAddress((void**)&Km, g_K);
    cudaGetSymbolAddress((void**)&Vm, g_V);
    cudaGetSymbolAddress((void**)&Om, g_O);

    // 1) LayerNorm
    ln_kernel<<<M_ROWS, 256>>>(X, ln_gamma, ln_beta, Xn);

    // 2) Q/K/V projections
    dim3 ggrid(D_MODEL / BN, M_ROWS / BM);
    gemm_nt_bias<<<ggrid, 256>>>(Xn, Wq, bq, Qm, M_ROWS, D_MODEL, D_MODEL);
    gemm_nt_bias<<<ggrid, 256>>>(Xn, Wk, bk, Km, M_ROWS, D_MODEL, D_MODEL);
    gemm_nt_bias<<<ggrid, 256>>>(Xn, Wv, bv, Vm, M_ROWS, D_MODEL, D_MODEL);

    // 3) causal attention
    dim3 agrid(SEQ / BR, N_HEADS, BATCH);
    attn_kernel<<<agrid, 64>>>(Qm, Km, Vm, Om);

    // 4) output projection -> d_out
    gemm_nt_bias<<<ggrid, 256>>>(Om, Wo, bo, out, M_ROWS, D_MODEL, D_MODEL);
}

// round 2
// speedup vs baseline: 1.2105x; 1.2105x over previous
#include <cuda_runtime.h>
#include <math.h>

#define D_MODEL 1024
#define N_HEADS 16
#define D_HEAD  64
#define BATCH   4
#define SEQ     2048
#define M_ROWS  (BATCH * SEQ)   // 8192

typedef unsigned long long u64;

// ---------------- f32x2 packed helpers (sm_100+) ----------------
__device__ __forceinline__ u64 ffma2(u64 a, u64 b, u64 c) {
    u64 d;
    asm("fma.rn.f32x2 %0, %1, %2, %3;" : "=l"(d) : "l"(a), "l"(b), "l"(c));
    return d;
}
__device__ __forceinline__ u64 fmul2(u64 a, u64 b) {
    u64 d;
    asm("mul.rn.f32x2 %0, %1, %2;" : "=l"(d) : "l"(a), "l"(b));
    return d;
}
__device__ __forceinline__ u64 fadd2(u64 a, u64 b) {
    u64 d;
    asm("add.rn.f32x2 %0, %1, %2;" : "=l"(d) : "l"(a), "l"(b));
    return d;
}
__device__ __forceinline__ u64 pack2(float x, float y) {
    u64 r;
    asm("mov.b64 %0, {%1, %2};" : "=l"(r) : "r"(__float_as_uint(x)), "r"(__float_as_uint(y)));
    return r;
}
__device__ __forceinline__ float2 unpack2(u64 v) {
    unsigned lo, hi;
    asm("mov.b64 {%0, %1}, %2;" : "=r"(lo), "=r"(hi) : "l"(v));
    float2 r; r.x = __uint_as_float(lo); r.y = __uint_as_float(hi);
    return r;
}

// ---------------- scratch (device globals; no allocation) ----------------
__device__ float g_Xn[M_ROWS * D_MODEL];
__device__ float g_Q [M_ROWS * D_MODEL];
__device__ float g_K [M_ROWS * D_MODEL];
__device__ float g_V [M_ROWS * D_MODEL];
__device__ float g_O [M_ROWS * D_MODEL];

// ---------------- LayerNorm ----------------
__global__ __launch_bounds__(256) void ln_kernel(
    const float* __restrict__ X, const float* __restrict__ gamma,
    const float* __restrict__ beta, float* __restrict__ Xn)
{
    int row = blockIdx.x;
    int tid = threadIdx.x;
    const float4* xr = reinterpret_cast<const float4*>(X + (size_t)row * D_MODEL);
    float4 v = xr[tid];

    float s  = v.x + v.y + v.z + v.w;
    float sq = v.x*v.x + v.y*v.y + v.z*v.z + v.w*v.w;

    #pragma unroll
    for (int o = 16; o > 0; o >>= 1) {
        s  += __shfl_xor_sync(0xffffffffu, s,  o);
        sq += __shfl_xor_sync(0xffffffffu, sq, o);
    }
    __shared__ float ss[8], ssq[8];
    int wid = tid >> 5, lid = tid & 31;
    if (lid == 0) { ss[wid] = s; ssq[wid] = sq; }
    __syncthreads();
    if (wid == 0) {
        float a = (lid < 8) ? ss[lid]  : 0.f;
        float b = (lid < 8) ? ssq[lid] : 0.f;
        #pragma unroll
        for (int o = 4; o > 0; o >>= 1) {
            a += __shfl_xor_sync(0xffffffffu, a, o);
            b += __shfl_xor_sync(0xffffffffu, b, o);
        }
        if (lid == 0) { ss[0] = a; ssq[0] = b; }
    }
    __syncthreads();
    float mean = ss[0] * (1.0f / D_MODEL);
    float var  = ssq[0] * (1.0f / D_MODEL) - mean * mean;
    float rstd = rsqrtf(var + 1e-5f);

    const float4* g4 = reinterpret_cast<const float4*>(gamma);
    const float4* b4 = reinterpret_cast<const float4*>(beta);
    float4 gv = g4[tid], bv = b4[tid];
    float4 o;
    o.x = (v.x - mean) * rstd * gv.x + bv.x;
    o.y = (v.y - mean) * rstd * gv.y + bv.y;
    o.z = (v.z - mean) * rstd * gv.z + bv.z;
    o.w = (v.w - mean) * rstd * gv.w + bv.w;
    reinterpret_cast<float4*>(Xn + (size_t)row * D_MODEL)[tid] = o;
}

// ---------------- SGEMM (f32x2): C[M,N] = A[M,K] @ W[N,K]^T + bias[N] ----------------
#define BM 128
#define BN 128
#define BK 16
#define TM 8
#define TN 8
#define TN2 4

__global__ __launch_bounds__(256) void gemm_nt_bias(
    const float* __restrict__ A, const float* __restrict__ W,
    const float* __restrict__ bias, float* __restrict__ C,
    int M, int N, int K)
{
    __shared__ float As[BK][BM];
    __shared__ float Bs[BK][BN];

    int tid = threadIdx.x;
    int bm = blockIdx.y * BM;
    int bn = blockIdx.x * BN;

    int lrow = tid >> 2;       // 0..63
    int lc4  = tid & 3;        // float4 index within BK

    int tx = tid & 15;
    int ty = tid >> 4;
    int tm = ty * TM;
    int tn = tx * TN;

    u64 acc2[TM][TN2];
    #pragma unroll
    for (int i = 0; i < TM; i++)
        #pragma unroll
        for (int p = 0; p < TN2; p++) acc2[i][p] = 0ull;

    for (int kt = 0; kt < K; kt += BK) {
        #pragma unroll
        for (int r = 0; r < 2; r++) {
            int arow = lrow + r * 64;
            float4 a = *reinterpret_cast<const float4*>(
                A + (size_t)(bm + arow) * K + kt + lc4 * 4);
            As[lc4*4+0][arow] = a.x;
            As[lc4*4+1][arow] = a.y;
            As[lc4*4+2][arow] = a.z;
            As[lc4*4+3][arow] = a.w;
            float4 b = *reinterpret_cast<const float4*>(
                W + (size_t)(bn + arow) * K + kt + lc4 * 4);
            Bs[lc4*4+0][arow] = b.x;
            Bs[lc4*4+1][arow] = b.y;
            Bs[lc4*4+2][arow] = b.z;
            Bs[lc4*4+3][arow] = b.w;
        }
        __syncthreads();

        #pragma unroll
        for (int kk = 0; kk < BK; kk++) {
            float4 a0 = *reinterpret_cast<const float4*>(&As[kk][tm]);
            float4 a1 = *reinterpret_cast<const float4*>(&As[kk][tm + 4]);
            ulonglong2 b0 = *reinterpret_cast<const ulonglong2*>(&Bs[kk][tn]);
            ulonglong2 b1 = *reinterpret_cast<const ulonglong2*>(&Bs[kk][tn + 4]);
            u64 rb[TN2] = { b0.x, b0.y, b1.x, b1.y };
            float ra[TM] = { a0.x, a0.y, a0.z, a0.w, a1.x, a1.y, a1.z, a1.w };
            #pragma unroll
            for (int i = 0; i < TM; i++) {
                u64 ad = pack2(ra[i], ra[i]);
                #pragma unroll
                for (int p = 0; p < TN2; p++)
                    acc2[i][p] = ffma2(ad, rb[p], acc2[i][p]);
            }
        }
        __syncthreads();
    }

    #pragma unroll
    for (int i = 0; i < TM; i++) {
        float* crow = C + (size_t)(bm + tm + i) * N + bn + tn;
        #pragma unroll
        for (int p = 0; p < TN2; p += 2) {
            float2 v0 = unpack2(acc2[i][p]);
            float2 v1 = unpack2(acc2[i][p + 1]);
            int j = p * 2;
            float4 o;
            o.x = v0.x + bias[bn + tn + j + 0];
            o.y = v0.y + bias[bn + tn + j + 1];
            o.z = v1.x + bias[bn + tn + j + 2];
            o.w = v1.y + bias[bn + tn + j + 3];
            *reinterpret_cast<float4*>(crow + j) = o;
        }
    }
}

// ---------------- Causal flash attention (f32x2, chunked online softmax) ----------------
#define ABR 128   // queries per block, 1/thread
#define ABC 32    // keys per smem tile
#define CH  8     // softmax-rescale chunk

__global__ __launch_bounds__(128) void attn_kernel(
    const float* __restrict__ Q, const float* __restrict__ K,
    const float* __restrict__ V, float* __restrict__ O)
{
    int qt = blockIdx.x;
    int h  = blockIdx.y;
    int b  = blockIdx.z;
    int row = qt * ABR + threadIdx.x;

    const float scale = 0.125f;   // 1/sqrt(64)

    __shared__ float Ks[ABC][D_HEAD];
    __shared__ float Vs[ABC][D_HEAD];

    // q packed & pre-scaled: 32 x f32x2
    u64 q2[32];
    {
        const float4* qp = reinterpret_cast<const float4*>(
            Q + ((size_t)(b * SEQ + row)) * D_MODEL + h * D_HEAD);
        #pragma unroll
        for (int c = 0; c < 16; c++) {
            float4 v = qp[c];
            q2[2*c]   = pack2(v.x * scale, v.y * scale);
            q2[2*c+1] = pack2(v.z * scale, v.w * scale);
        }
    }

    u64 acc2[32];
    #pragma unroll
    for (int c = 0; c < 32; c++) acc2[c] = 0ull;
    float m = -INFINITY, l = 0.f;

    int kend = qt * ABR + ABR;
    for (int kbase = 0; kbase < kend; kbase += ABC) {
        __syncthreads();
        // cooperative tile load: 32 rows x 16 float4 = 512 float4 / 128 threads
        #pragma unroll
        for (int it = 0; it < 4; it++) {
            int i = threadIdx.x + it * 128;
            int j = i >> 4, c = i & 15;
            size_t g = ((size_t)(b * SEQ + kbase + j)) * D_MODEL + h * D_HEAD + c * 4;
            reinterpret_cast<float4*>(Ks[j])[c] = *reinterpret_cast<const float4*>(K + g);
            reinterpret_cast<float4*>(Vs[j])[c] = *reinterpret_cast<const float4*>(V + g);
        }
        __syncthreads();

        #pragma unroll
        for (int ch = 0; ch < ABC / CH; ch++) {
            float sc[CH];
            float cmax = -INFINITY;
            #pragma unroll
            for (int jj = 0; jj < CH; jj++) {
                int j = ch * CH + jj;
                const u64* kr = reinterpret_cast<const u64*>(Ks[j]);
                u64 d2a = 0ull, d2b = 0ull;
                #pragma unroll
                for (int c = 0; c < 16; c++) {
                    d2a = ffma2(q2[2*c],   kr[2*c],   d2a);
                    d2b = ffma2(q2[2*c+1], kr[2*c+1], d2b);
                }
                float2 dd = unpack2(fadd2(d2a, d2b));
                float s = dd.x + dd.y;
                s = (kbase + j <= row) ? s : -INFINITY;
                sc[jj] = s;
                cmax = fmaxf(cmax, s);
            }
            float mnew = fmaxf(m, cmax);
            float corr = __expf(m - mnew);
            l *= corr;
            u64 c2 = pack2(corr, corr);
            #pragma unroll
            for (int c = 0; c < 32; c++) acc2[c] = fmul2(acc2[c], c2);
            m = mnew;
            #pragma unroll
            for (int jj = 0; jj < CH; jj++) {
                float p = __expf(sc[jj] - mnew);
                l += p;
                u64 p2 = pack2(p, p);
                const u64* vr = reinterpret_cast<const u64*>(Vs[ch * CH + jj]);
                #pragma unroll
                for (int c = 0; c < 32; c++)
                    acc2[c] = ffma2(p2, vr[c], acc2[c]);
            }
        }
    }

    float inv = 1.f / l;
    float4* op = reinterpret_cast<float4*>(
        O + ((size_t)(b * SEQ + row)) * D_MODEL + h * D_HEAD);
    #pragma unroll
    for (int c = 0; c < 16; c++) {
        float2 a = unpack2(acc2[2*c]);
        float2 bb = unpack2(acc2[2*c+1]);
        float4 o;
        o.x = a.x * inv;  o.y = a.y * inv;
        o.z = bb.x * inv; o.w = bb.y * inv;
        op[c] = o;
    }
}

// ---------------- launch ----------------
extern "C" void kernel_launch(void* const* d_in, const int* in_sizes, int n_in,
                              void* d_out, int out_size)
{
    const float* X        = (const float*)d_in[0];
    const float* ln_gamma = (const float*)d_in[1];
    const float* ln_beta  = (const float*)d_in[2];
    const float* Wq       = (const float*)d_in[3];
    const float* bq       = (const float*)d_in[4];
    const float* Wk       = (const float*)d_in[5];
    const float* bk       = (const float*)d_in[6];
    const float* Wv       = (const float*)d_in[7];
    const float* bv       = (const float*)d_in[8];
    const float* Wo       = (const float*)d_in[9];
    const float* bo       = (const float*)d_in[10];
    float* out = (float*)d_out;

    float *Xn, *Qm, *Km, *Vm, *Om;
    cudaGetSymbolAddress((void**)&Xn, g_Xn);
    cudaGetSymbolAddress((void**)&Qm, g_Q);
    cudaGetSymbolAddress((void**)&Km, g_K);
    cudaGetSymbolAddress((void**)&Vm, g_V);
    cudaGetSymbolAddress((void**)&Om, g_O);

    ln_kernel<<<M_ROWS, 256>>>(X, ln_gamma, ln_beta, Xn);

    dim3 ggrid(D_MODEL / BN, M_ROWS / BM);
    gemm_nt_bias<<<ggrid, 256>>>(Xn, Wq, bq, Qm, M_ROWS, D_MODEL, D_MODEL);
    gemm_nt_bias<<<ggrid, 256>>>(Xn, Wk, bk, Km, M_ROWS, D_MODEL, D_MODEL);
    gemm_nt_bias<<<ggrid, 256>>>(Xn, Wv, bv, Vm, M_ROWS, D_MODEL, D_MODEL);

    dim3 agrid(SEQ / ABR, N_HEADS, BATCH);
    attn_kernel<<<agrid, 128>>>(Qm, Km, Vm, Om);

    gemm_nt_bias<<<ggrid, 256>>>(Om, Wo, bo, out, M_ROWS, D_MODEL, D_MODEL);
}

// round 4
// speedup vs baseline: 1.8002x; 1.4872x over previous
#include <cuda_runtime.h>
#include <math.h>
#include <stdint.h>

#define D_MODEL 1024
#define N_HEADS 16
#define D_HEAD  64
#define BATCH   4
#define SEQ     2048
#define M_ROWS  (BATCH * SEQ)   // 8192

typedef unsigned long long u64;

// ---------------- f32x2 packed helpers ----------------
__device__ __forceinline__ u64 ffma2(u64 a, u64 b, u64 c) {
    u64 d; asm("fma.rn.f32x2 %0, %1, %2, %3;" : "=l"(d) : "l"(a), "l"(b), "l"(c)); return d;
}
__device__ __forceinline__ u64 fmul2(u64 a, u64 b) {
    u64 d; asm("mul.rn.f32x2 %0, %1, %2;" : "=l"(d) : "l"(a), "l"(b)); return d;
}
__device__ __forceinline__ u64 fadd2(u64 a, u64 b) {
    u64 d; asm("add.rn.f32x2 %0, %1, %2;" : "=l"(d) : "l"(a), "l"(b)); return d;
}
__device__ __forceinline__ u64 pack2(float x, float y) {
    u64 r; asm("mov.b64 %0, {%1, %2};" : "=l"(r) : "r"(__float_as_uint(x)), "r"(__float_as_uint(y))); return r;
}
__device__ __forceinline__ float2 unpack2(u64 v) {
    unsigned lo, hi; asm("mov.b64 {%0, %1}, %2;" : "=r"(lo), "=r"(hi) : "l"(v));
    float2 r; r.x = __uint_as_float(lo); r.y = __uint_as_float(hi); return r;
}

// ---------------- mma.sync helpers (baseline PTX ISA, no tcgen05) ----------------
__device__ __forceinline__ uint32_t smem_u32(const void* p) {
    uint32_t a;
    asm("{ .reg .u64 t; cvta.to.shared.u64 t, %1; cvt.u32.u64 %0, t; }" : "=r"(a) : "l"(p));
    return a;
}
__device__ __forceinline__ uint32_t cvt_tf32(float f) {
    uint32_t o; asm("cvt.rna.tf32.f32 %0, %1;" : "=r"(o) : "f"(f)); return o;
}
__device__ __forceinline__ void sts_tf32x4(uint32_t addr, float4 v) {
    asm volatile("st.shared.v4.b32 [%0], {%1,%2,%3,%4};" :: "r"(addr),
        "r"(cvt_tf32(v.x)), "r"(cvt_tf32(v.y)), "r"(cvt_tf32(v.z)), "r"(cvt_tf32(v.w)));
}
__device__ __forceinline__ void ldmatrix_x4(uint32_t* r, uint32_t addr) {
    asm volatile("ldmatrix.sync.aligned.m8n8.x4.shared.b16 {%0,%1,%2,%3}, [%4];"
        : "=r"(r[0]), "=r"(r[1]), "=r"(r[2]), "=r"(r[3]) : "r"(addr));
}
__device__ __forceinline__ void mma_tf32(float* c, const uint32_t* a, uint32_t b0, uint32_t b1) {
    asm volatile("mma.sync.aligned.m16n8k8.row.col.f32.tf32.tf32.f32 "
        "{%0,%1,%2,%3}, {%4,%5,%6,%7}, {%8,%9}, {%0,%1,%2,%3};"
        : "+f"(c[0]), "+f"(c[1]), "+f"(c[2]), "+f"(c[3])
        : "r"(a[0]), "r"(a[1]), "r"(a[2]), "r"(a[3]), "r"(b0), "r"(b1));
}

// ---------------- scratch ----------------
__device__ float g_Xn[M_ROWS * D_MODEL];
__device__ float g_Q [M_ROWS * D_MODEL];
__device__ float g_K [M_ROWS * D_MODEL];
__device__ float g_V [M_ROWS * D_MODEL];
__device__ float g_O [M_ROWS * D_MODEL];

// ---------------- LayerNorm ----------------
__global__ __launch_bounds__(256) void ln_kernel(
    const float* __restrict__ X, const float* __restrict__ gamma,
    const float* __restrict__ beta, float* __restrict__ Xn)
{
    int row = blockIdx.x;
    int tid = threadIdx.x;
    const float4* xr = reinterpret_cast<const float4*>(X + (size_t)row * D_MODEL);
    float4 v = xr[tid];

    float s  = v.x + v.y + v.z + v.w;
    float sq = v.x*v.x + v.y*v.y + v.z*v.z + v.w*v.w;

    #pragma unroll
    for (int o = 16; o > 0; o >>= 1) {
        s  += __shfl_xor_sync(0xffffffffu, s,  o);
        sq += __shfl_xor_sync(0xffffffffu, sq, o);
    }
    __shared__ float ss[8], ssq[8];
    int wid = tid >> 5, lid = tid & 31;
    if (lid == 0) { ss[wid] = s; ssq[wid] = sq; }
    __syncthreads();
    if (wid == 0) {
        float a = (lid < 8) ? ss[lid]  : 0.f;
        float b = (lid < 8) ? ssq[lid] : 0.f;
        #pragma unroll
        for (int o = 4; o > 0; o >>= 1) {
            a += __shfl_xor_sync(0xffffffffu, a, o);
            b += __shfl_xor_sync(0xffffffffu, b, o);
        }
        if (lid == 0) { ss[0] = a; ssq[0] = b; }
    }
    __syncthreads();
    float mean = ss[0] * (1.0f / D_MODEL);
    float var  = ssq[0] * (1.0f / D_MODEL) - mean * mean;
    float rstd = rsqrtf(var + 1e-5f);

    const float4* g4 = reinterpret_cast<const float4*>(gamma);
    const float4* b4 = reinterpret_cast<const float4*>(beta);
    float4 gv = g4[tid], bv = b4[tid];
    float4 o;
    o.x = (v.x - mean) * rstd * gv.x + bv.x;
    o.y = (v.y - mean) * rstd * gv.y + bv.y;
    o.z = (v.z - mean) * rstd * gv.z + bv.z;
    o.w = (v.w - mean) * rstd * gv.w + bv.w;
    reinterpret_cast<float4*>(Xn + (size_t)row * D_MODEL)[tid] = o;
}

// ---------------- tf32 mma.sync GEMM: C[M,1024] = A @ W^T + bias ----------------
// CTA 128x128, BK=32, 256 threads (8 warps, 2m x 4n of 64x32 warp tiles),
// SW128-swizzled smem, double-buffered, ldmatrix-fed fragments.
#define GT_STRIDE 16384   // bytes per 128x32 tf32 tile

__global__ __launch_bounds__(256) void gemm_mma(
    const float* __restrict__ A, const float* __restrict__ W,
    const float* __restrict__ bias, float* __restrict__ C)
{
    extern __shared__ char sm[];
    uint32_t sbase = smem_u32(sm);

    const int tid = threadIdx.x;
    const int lane = tid & 31;
    const int wid = tid >> 5;
    const int warp_m = wid >> 2;   // 0..1 -> 64-row slab
    const int warp_n = wid & 3;    // 0..3 -> 32-col slab
    const int bm = blockIdx.y * 128;
    const int bn = blockIdx.x * 128;

    // ldmatrix per-lane geometry (block = lane/8)
    const int Lg = lane >> 3;
    const int Lr = lane & 7;
    const int a_row = ((Lg & 1) << 3) + Lr;   // 0..15
    const int a_col = (Lg >> 1) << 2;         // 0 or 4 (tf32 cols)
    const int b_row = ((Lg >> 1) << 3) + Lr;
    const int b_col = (Lg & 1) << 2;

    const float4* A4 = reinterpret_cast<const float4*>(A);
    const float4* W4 = reinterpret_cast<const float4*>(W);

    float acc[4][4][4];
    #pragma unroll
    for (int mt = 0; mt < 4; mt++)
        #pragma unroll
        for (int nt = 0; nt < 4; nt++)
            #pragma unroll
            for (int e = 0; e < 4; e++) acc[mt][nt][e] = 0.f;

    float4 pa[4], pb[4];

    // prologue: load k-tile 0
    #pragma unroll
    for (int i = 0; i < 4; i++) {
        int idx = tid + i * 256;
        int r = idx >> 3, j = idx & 7;
        pa[i] = A4[(size_t)(bm + r) * 256 + j];
        pb[i] = W4[(size_t)(bn + r) * 256 + j];
    }
    #pragma unroll
    for (int i = 0; i < 4; i++) {
        int idx = tid + i * 256;
        int r = idx >> 3, j = idx & 7;
        uint32_t off = (uint32_t)(r * 128 + j * 16);
        uint32_t sw = off ^ ((off >> 3) & 0x70);
        sts_tf32x4(sbase + sw, pa[i]);
        sts_tf32x4(sbase + GT_STRIDE + sw, pb[i]);
    }
    __syncthreads();

    for (int kt = 0; kt < 32; kt++) {
        int buf = kt & 1;
        if (kt < 31) {
            #pragma unroll
            for (int i = 0; i < 4; i++) {
                int idx = tid + i * 256;
                int r = idx >> 3, j = idx & 7;
                pa[i] = A4[(size_t)(bm + r) * 256 + (kt + 1) * 8 + j];
                pb[i] = W4[(size_t)(bn + r) * 256 + (kt + 1) * 8 + j];
            }
        }
        uint32_t abase = sbase + buf * (2 * GT_STRIDE);
        uint32_t bbase = abase + GT_STRIDE;

        #pragma unroll
        for (int ks = 0; ks < 4; ks++) {
            uint32_t af[4][4];
            #pragma unroll
            for (int mt = 0; mt < 4; mt++) {
                uint32_t off = (uint32_t)((warp_m * 64 + mt * 16 + a_row) * 128
                                          + (ks * 8 + a_col) * 4);
                ldmatrix_x4(af[mt], abase + (off ^ ((off >> 3) & 0x70)));
            }
            uint32_t bf[2][4];
            #pragma unroll
            for (int np = 0; np < 2; np++) {
                uint32_t off = (uint32_t)((warp_n * 32 + np * 16 + b_row) * 128
                                          + (ks * 8 + b_col) * 4);
                ldmatrix_x4(bf[np], bbase + (off ^ ((off >> 3) & 0x70)));
            }
            #pragma unroll
            for (int mt = 0; mt < 4; mt++)
                #pragma unroll
                for (int nt = 0; nt < 4; nt++)
                    mma_tf32(acc[mt][nt], af[mt],
                             bf[nt >> 1][(nt & 1) * 2], bf[nt >> 1][(nt & 1) * 2 + 1]);
        }

        if (kt < 31) {
            #pragma unroll
            for (int i = 0; i < 4; i++) {
                int idx = tid + i * 256;
                int r = idx >> 3, j = idx & 7;
                uint32_t off = (uint32_t)(r * 128 + j * 16);
                uint32_t sw = off ^ ((off >> 3) & 0x70);
                uint32_t dst = sbase + (buf ^ 1) * (2 * GT_STRIDE);
                sts_tf32x4(dst + sw, pa[i]);
                sts_tf32x4(dst + GT_STRIDE + sw, pb[i]);
            }
            __syncthreads();
        }
    }

    // epilogue: write fragments + bias
    #pragma unroll
    for (int mt = 0; mt < 4; mt++) {
        int r0 = bm + warp_m * 64 + mt * 16 + (lane >> 2);
        #pragma unroll
        for (int nt = 0; nt < 4; nt++) {
            int c0 = bn + warp_n * 32 + nt * 8 + ((lane & 3) << 1);
            float bx = bias[c0], by = bias[c0 + 1];
            float2 v0 = make_float2(acc[mt][nt][0] + bx, acc[mt][nt][1] + by);
            float2 v1 = make_float2(acc[mt][nt][2] + bx, acc[mt][nt][3] + by);
            *reinterpret_cast<float2*>(C + (size_t)r0 * D_MODEL + c0) = v0;
            *reinterpret_cast<float2*>(C + (size_t)(r0 + 8) * D_MODEL + c0) = v1;
        }
    }
}

// ---------------- Causal flash attention (f32x2, chunked online softmax) ----------------
#define ABR 128
#define ABC 32
#define CH  8

__global__ __launch_bounds__(128) void attn_kernel(
    const float* __restrict__ Q, const float* __restrict__ K,
    const float* __restrict__ V, float* __restrict__ O)
{
    int qt = blockIdx.x;
    int h  = blockIdx.y;
    int b  = blockIdx.z;
    int row = qt * ABR + threadIdx.x;

    const float scale = 0.125f;

    __shared__ float Ks[ABC][D_HEAD];
    __shared__ float Vs[ABC][D_HEAD];

    u64 q2[32];
    {
        const float4* qp = reinterpret_cast<const float4*>(
            Q + ((size_t)(b * SEQ + row)) * D_MODEL + h * D_HEAD);
        #pragma unroll
        for (int c = 0; c < 16; c++) {
            float4 v = qp[c];
            q2[2*c]   = pack2(v.x * scale, v.y * scale);
            q2[2*c+1] = pack2(v.z * scale, v.w * scale);
        }
    }

    u64 acc2[32];
    #pragma unroll
    for (int c = 0; c < 32; c++) acc2[c] = 0ull;
    float m = -INFINITY, l = 0.f;

    int kend = qt * ABR + ABR;
    for (int kbase = 0; kbase < kend; kbase += ABC) {
        __syncthreads();
        #pragma unroll
        for (int it = 0; it < 4; it++) {
            int i = threadIdx.x + it * 128;
            int j = i >> 4, c = i & 15;
            size_t g = ((size_t)(b * SEQ + kbase + j)) * D_MODEL + h * D_HEAD + c * 4;
            reinterpret_cast<float4*>(Ks[j])[c] = *reinterpret_cast<const float4*>(K + g);
            reinterpret_cast<float4*>(Vs[j])[c] = *reinterpret_cast<const float4*>(V + g);
        }
        __syncthreads();

        #pragma unroll
        for (int ch = 0; ch < ABC / CH; ch++) {
            float sc[CH];
            float cmax = -INFINITY;
            #pragma unroll
            for (int jj = 0; jj < CH; jj++) {
                int j = ch * CH + jj;
                const u64* kr = reinterpret_cast<const u64*>(Ks[j]);
                u64 d2a = 0ull, d2b = 0ull;
                #pragma unroll
                for (int c = 0; c < 16; c++) {
                    d2a = ffma2(q2[2*c],   kr[2*c],   d2a);
                    d2b = ffma2(q2[2*c+1], kr[2*c+1], d2b);
                }
                float2 dd = unpack2(fadd2(d2a, d2b));
                float s = dd.x + dd.y;
                s = (kbase + j <= row) ? s : -INFINITY;
                sc[jj] = s;
                cmax = fmaxf(cmax, s);
            }
            float mnew = fmaxf(m, cmax);
            float corr = __expf(m - mnew);
            l *= corr;
            u64 c2 = pack2(corr, corr);
            #pragma unroll
            for (int c = 0; c < 32; c++) acc2[c] = fmul2(acc2[c], c2);
            m = mnew;
            #pragma unroll
            for (int jj = 0; jj < CH; jj++) {
                float p = __expf(sc[jj] - mnew);
                l += p;
                u64 p2 = pack2(p, p);
                const u64* vr = reinterpret_cast<const u64*>(Vs[ch * CH + jj]);
                #pragma unroll
                for (int c = 0; c < 32; c++)
                    acc2[c] = ffma2(p2, vr[c], acc2[c]);
            }
        }
    }

    float inv = 1.f / l;
    float4* op = reinterpret_cast<float4*>(
        O + ((size_t)(b * SEQ + row)) * D_MODEL + h * D_HEAD);
    #pragma unroll
    for (int c = 0; c < 16; c++) {
        float2 a = unpack2(acc2[2*c]);
        float2 bb = unpack2(acc2[2*c+1]);
        float4 o;
        o.x = a.x * inv;  o.y = a.y * inv;
        o.z = bb.x * inv; o.w = bb.y * inv;
        op[c] = o;
    }
}

// ---------------- launch ----------------
extern "C" void kernel_launch(void* const* d_in, const int* in_sizes, int n_in,
                              void* d_out, int out_size)
{
    const float* X        = (const float*)d_in[0];
    const float* ln_gamma = (const float*)d_in[1];
    const float* ln_beta  = (const float*)d_in[2];
    const float* Wq       = (const float*)d_in[3];
    const float* bq       = (const float*)d_in[4];
    const float* Wk       = (const float*)d_in[5];
    const float* bk       = (const float*)d_in[6];
    const float* Wv       = (const float*)d_in[7];
    const float* bv       = (const float*)d_in[8];
    const float* Wo       = (const float*)d_in[9];
    const float* bo       = (const float*)d_in[10];
    float* out = (float*)d_out;

    float *Xn, *Qm, *Km, *Vm, *Om;
    cudaGetSymbolAddress((void**)&Xn, g_Xn);
    cudaGetSymbolAddress((void**)&Qm, g_Q);
    cudaGetSymbolAddress((void**)&Km, g_K);
    cudaGetSymbolAddress((void**)&Vm, g_V);
    cudaGetSymbolAddress((void**)&Om, g_O);

    const int gsmem = 4 * GT_STRIDE;   // 64KB
    cudaFuncSetAttribute(gemm_mma, cudaFuncAttributeMaxDynamicSharedMemorySize, gsmem);

    ln_kernel<<<M_ROWS, 256>>>(X, ln_gamma, ln_beta, Xn);

    dim3 ggrid(D_MODEL / 128, M_ROWS / 128);
    gemm_mma<<<ggrid, 256, gsmem>>>(Xn, Wq, bq, Qm);
    gemm_mma<<<ggrid, 256, gsmem>>>(Xn, Wk, bk, Km);
    gemm_mma<<<ggrid, 256, gsmem>>>(Xn, Wv, bv, Vm);

    dim3 agrid(SEQ / ABR, N_HEADS, BATCH);
    attn_kernel<<<agrid, 128>>>(Qm, Km, Vm, Om);

    gemm_mma<<<ggrid, 256, gsmem>>>(Om, Wo, bo, out);
}

// round 5
// speedup vs baseline: 4.6870x; 2.6036x over previous
#include <cuda_runtime.h>
#include <math.h>
#include <stdint.h>

#define D_MODEL 1024
#define N_HEADS 16
#define D_HEAD  64
#define BATCH   4
#define SEQ     2048
#define M_ROWS  (BATCH * SEQ)   // 8192

// ---------------- mma.sync helpers (baseline PTX ISA) ----------------
__device__ __forceinline__ uint32_t smem_u32(const void* p) {
    uint32_t a;
    asm("{ .reg .u64 t; cvta.to.shared.u64 t, %1; cvt.u32.u64 %0, t; }" : "=r"(a) : "l"(p));
    return a;
}
__device__ __forceinline__ uint32_t cvt_tf32(float f) {
    uint32_t o; asm("cvt.rna.tf32.f32 %0, %1;" : "=r"(o) : "f"(f)); return o;
}
__device__ __forceinline__ void sts_tf32x4(uint32_t addr, float4 v) {
    asm volatile("st.shared.v4.b32 [%0], {%1,%2,%3,%4};" :: "r"(addr),
        "r"(cvt_tf32(v.x)), "r"(cvt_tf32(v.y)), "r"(cvt_tf32(v.z)), "r"(cvt_tf32(v.w)));
}
__device__ __forceinline__ void sts_tf32x2(uint32_t addr, float x, float y) {
    asm volatile("st.shared.v2.b32 [%0], {%1,%2};" :: "r"(addr),
        "r"(cvt_tf32(x)), "r"(cvt_tf32(y)));
}
__device__ __forceinline__ void sts_tf32(uint32_t addr, float x) {
    asm volatile("st.shared.b32 [%0], %1;" :: "r"(addr), "r"(cvt_tf32(x)));
}
__device__ __forceinline__ void ldmatrix_x4(uint32_t* r, uint32_t addr) {
    asm volatile("ldmatrix.sync.aligned.m8n8.x4.shared.b16 {%0,%1,%2,%3}, [%4];"
        : "=r"(r[0]), "=r"(r[1]), "=r"(r[2]), "=r"(r[3]) : "r"(addr));
}
__device__ __forceinline__ void mma_tf32(float* c, const uint32_t* a, uint32_t b0, uint32_t b1) {
    asm volatile("mma.sync.aligned.m16n8k8.row.col.f32.tf32.tf32.f32 "
        "{%0,%1,%2,%3}, {%4,%5,%6,%7}, {%8,%9}, {%0,%1,%2,%3};"
        : "+f"(c[0]), "+f"(c[1]), "+f"(c[2]), "+f"(c[3])
        : "r"(a[0]), "r"(a[1]), "r"(a[2]), "r"(a[3]), "r"(b0), "r"(b1));
}
__device__ __forceinline__ uint32_t sw128(uint32_t off) { return off ^ ((off >> 3) & 0x70); }

// ---------------- scratch ----------------
__device__ float g_Xn[M_ROWS * D_MODEL];
__device__ float g_Q [M_ROWS * D_MODEL];
__device__ float g_K [M_ROWS * D_MODEL];
__device__ float g_V [M_ROWS * D_MODEL];
__device__ float g_O [M_ROWS * D_MODEL];

// ---------------- LayerNorm ----------------
__global__ __launch_bounds__(256) void ln_kernel(
    const float* __restrict__ X, const float* __restrict__ gamma,
    const float* __restrict__ beta, float* __restrict__ Xn)
{
    int row = blockIdx.x;
    int tid = threadIdx.x;
    const float4* xr = reinterpret_cast<const float4*>(X + (size_t)row * D_MODEL);
    float4 v = xr[tid];

    float s  = v.x + v.y + v.z + v.w;
    float sq = v.x*v.x + v.y*v.y + v.z*v.z + v.w*v.w;

    #pragma unroll
    for (int o = 16; o > 0; o >>= 1) {
        s  += __shfl_xor_sync(0xffffffffu, s,  o);
        sq += __shfl_xor_sync(0xffffffffu, sq, o);
    }
    __shared__ float ss[8], ssq[8];
    int wid = tid >> 5, lid = tid & 31;
    if (lid == 0) { ss[wid] = s; ssq[wid] = sq; }
    __syncthreads();
    if (wid == 0) {
        float a = (lid < 8) ? ss[lid]  : 0.f;
        float b = (lid < 8) ? ssq[lid] : 0.f;
        #pragma unroll
        for (int o = 4; o > 0; o >>= 1) {
            a += __shfl_xor_sync(0xffffffffu, a, o);
            b += __shfl_xor_sync(0xffffffffu, b, o);
        }
        if (lid == 0) { ss[0] = a; ssq[0] = b; }
    }
    __syncthreads();
    float mean = ss[0] * (1.0f / D_MODEL);
    float var  = ssq[0] * (1.0f / D_MODEL) - mean * mean;
    float rstd = rsqrtf(var + 1e-5f);

    const float4* g4 = reinterpret_cast<const float4*>(gamma);
    const float4* b4 = reinterpret_cast<const float4*>(beta);
    float4 gv = g4[tid], bv = b4[tid];
    float4 o;
    o.x = (v.x - mean) * rstd * gv.x + bv.x;
    o.y = (v.y - mean) * rstd * gv.y + bv.y;
    o.z = (v.z - mean) * rstd * gv.z + bv.z;
    o.w = (v.w - mean) * rstd * gv.w + bv.w;
    reinterpret_cast<float4*>(Xn + (size_t)row * D_MODEL)[tid] = o;
}

// ---------------- tf32 mma.sync GEMM (unchanged from R4) ----------------
#define GT_STRIDE 16384

__global__ __launch_bounds__(256) void gemm_mma(
    const float* __restrict__ A, const float* __restrict__ W,
    const float* __restrict__ bias, float* __restrict__ C)
{
    extern __shared__ char sm[];
    uint32_t sbase = smem_u32(sm);

    const int tid = threadIdx.x;
    const int lane = tid & 31;
    const int wid = tid >> 5;
    const int warp_m = wid >> 2;
    const int warp_n = wid & 3;
    const int bm = blockIdx.y * 128;
    const int bn = blockIdx.x * 128;

    const int Lg = lane >> 3;
    const int Lr = lane & 7;
    const int a_row = ((Lg & 1) << 3) + Lr;
    const int a_col = (Lg >> 1) << 2;
    const int b_row = ((Lg >> 1) << 3) + Lr;
    const int b_col = (Lg & 1) << 2;

    const float4* A4 = reinterpret_cast<const float4*>(A);
    const float4* W4 = reinterpret_cast<const float4*>(W);

    float acc[4][4][4];
    #pragma unroll
    for (int mt = 0; mt < 4; mt++)
        #pragma unroll
        for (int nt = 0; nt < 4; nt++)
            #pragma unroll
            for (int e = 0; e < 4; e++) acc[mt][nt][e] = 0.f;

    float4 pa[4], pb[4];

    #pragma unroll
    for (int i = 0; i < 4; i++) {
        int idx = tid + i * 256;
        int r = idx >> 3, j = idx & 7;
        pa[i] = A4[(size_t)(bm + r) * 256 + j];
        pb[i] = W4[(size_t)(bn + r) * 256 + j];
    }
    #pragma unroll
    for (int i = 0; i < 4; i++) {
        int idx = tid + i * 256;
        int r = idx >> 3, j = idx & 7;
        uint32_t sw = sw128((uint32_t)(r * 128 + j * 16));
        sts_tf32x4(sbase + sw, pa[i]);
        sts_tf32x4(sbase + GT_STRIDE + sw, pb[i]);
    }
    __syncthreads();

    for (int kt = 0; kt < 32; kt++) {
        int buf = kt & 1;
        if (kt < 31) {
            #pragma unroll
            for (int i = 0; i < 4; i++) {
                int idx = tid + i * 256;
                int r = idx >> 3, j = idx & 7;
                pa[i] = A4[(size_t)(bm + r) * 256 + (kt + 1) * 8 + j];
                pb[i] = W4[(size_t)(bn + r) * 256 + (kt + 1) * 8 + j];
            }
        }
        uint32_t abase = sbase + buf * (2 * GT_STRIDE);
        uint32_t bbase = abase + GT_STRIDE;

        #pragma unroll
        for (int ks = 0; ks < 4; ks++) {
            uint32_t af[4][4];
            #pragma unroll
            for (int mt = 0; mt < 4; mt++) {
                uint32_t off = (uint32_t)((warp_m * 64 + mt * 16 + a_row) * 128
                                          + (ks * 8 + a_col) * 4);
                ldmatrix_x4(af[mt], abase + sw128(off));
            }
            uint32_t bf[2][4];
            #pragma unroll
            for (int np = 0; np < 2; np++) {
                uint32_t off = (uint32_t)((warp_n * 32 + np * 16 + b_row) * 128
                                          + (ks * 8 + b_col) * 4);
                ldmatrix_x4(bf[np], bbase + sw128(off));
            }
            #pragma unroll
            for (int mt = 0; mt < 4; mt++)
                #pragma unroll
                for (int nt = 0; nt < 4; nt++)
                    mma_tf32(acc[mt][nt], af[mt],
                             bf[nt >> 1][(nt & 1) * 2], bf[nt >> 1][(nt & 1) * 2 + 1]);
        }

        if (kt < 31) {
            #pragma unroll
            for (int i = 0; i < 4; i++) {
                int idx = tid + i * 256;
                int r = idx >> 3, j = idx & 7;
                uint32_t sw = sw128((uint32_t)(r * 128 + j * 16));
                uint32_t dst = sbase + (buf ^ 1) * (2 * GT_STRIDE);
                sts_tf32x4(dst + sw, pa[i]);
                sts_tf32x4(dst + GT_STRIDE + sw, pb[i]);
            }
            __syncthreads();
        }
    }

    #pragma unroll
    for (int mt = 0; mt < 4; mt++) {
        int r0 = bm + warp_m * 64 + mt * 16 + (lane >> 2);
        #pragma unroll
        for (int nt = 0; nt < 4; nt++) {
            int c0 = bn + warp_n * 32 + nt * 8 + ((lane & 3) << 1);
            float bx = bias[c0], by = bias[c0 + 1];
            float2 v0 = make_float2(acc[mt][nt][0] + bx, acc[mt][nt][1] + by);
            float2 v1 = make_float2(acc[mt][nt][2] + bx, acc[mt][nt][3] + by);
            *reinterpret_cast<float2*>(C + (size_t)r0 * D_MODEL + c0) = v0;
            *reinterpret_cast<float2*>(C + (size_t)(r0 + 8) * D_MODEL + c0) = v1;
        }
    }
}

// ---------------- tf32 mma.sync causal flash attention ----------------
// CTA: 64 query rows of one (b,h); 4 warps x 16 rows; 64-key blocks.
// smem: K tile [64 keys][64 d] (2 col-panels of 128B rows, swizzled)
//       VT tile [64 d][64 keys] (2 key-panels)
//       P staging: per warp 16x64 tf32 (2 key-panels)
__global__ __launch_bounds__(128) void attn_mma(
    const float* __restrict__ Q, const float* __restrict__ K,
    const float* __restrict__ V, float* __restrict__ O)
{
    __shared__ __align__(1024) char smem_raw[49152];
    uint32_t sb  = smem_u32(smem_raw);
    uint32_t Kb  = sb;            // 16KB
    uint32_t VTb = sb + 16384;    // 16KB
    uint32_t Pb  = sb + 32768;    // 16KB (4KB per warp)

    const int tid = threadIdx.x;
    const int lane = tid & 31;
    const int wid = tid >> 5;
    const int qt = blockIdx.x;
    const int h  = blockIdx.y;
    const int b  = blockIdx.z;

    const int Lg = lane >> 3;
    const int Lr = lane & 7;
    const int a_row = ((Lg & 1) << 3) + Lr;
    const int a_col = (Lg >> 1) << 2;
    const int b_row = ((Lg >> 1) << 3) + Lr;
    const int b_col = (Lg & 1) << 2;

    const int r_in = lane >> 2;        // fragment row within 16 (0..7)
    const int c2   = (lane & 3) << 1;  // fragment col pair base (0,2,4,6)

    const float scale = 0.125f;

    // ---- load Q tile (scaled, tf32) into K region, extract fragments ----
    {
        const float* Qg = Q + ((size_t)(b * SEQ + qt * 64)) * D_MODEL + h * D_HEAD;
        #pragma unroll
        for (int i = 0; i < 8; i++) {
            int idx = tid + i * 128;
            int r = idx >> 4, c4 = idx & 15;
            float4 v = *reinterpret_cast<const float4*>(Qg + (size_t)r * D_MODEL + c4 * 4);
            v.x *= scale; v.y *= scale; v.z *= scale; v.w *= scale;
            uint32_t off = (uint32_t)((c4 >> 3) * 8192 + r * 128 + (c4 & 7) * 16);
            sts_tf32x4(Kb + ((off & 8191) ^ (((off & 8191) >> 3) & 0x70)) + (off & ~8191u), v);
        }
    }
    __syncthreads();
    uint32_t qf[8][4];
    #pragma unroll
    for (int ks = 0; ks < 8; ks++) {
        uint32_t off = (uint32_t)((wid * 16 + a_row) * 128 + ((ks & 3) * 8 + a_col) * 4);
        ldmatrix_x4(qf[ks], Kb + (ks >> 2) * 8192 + sw128(off));
    }
    __syncthreads();

    float accv[8][4];
    #pragma unroll
    for (int nt = 0; nt < 8; nt++)
        #pragma unroll
        for (int e = 0; e < 4; e++) accv[nt][e] = 0.f;
    float m0 = -INFINITY, m1 = -INFINITY, l0 = 0.f, l1 = 0.f;

    const uint32_t Pw = Pb + wid * 4096;

    for (int kb = 0; kb <= qt; kb++) {
        const float* Kg = K + ((size_t)(b * SEQ + kb * 64)) * D_MODEL + h * D_HEAD;
        const float* Vg = V + ((size_t)(b * SEQ + kb * 64)) * D_MODEL + h * D_HEAD;

        // K tile: [key][d], coalesced loads, v4 swizzled stores
        #pragma unroll
        for (int i = 0; i < 8; i++) {
            int idx = tid + i * 128;
            int r = idx >> 4, c4 = idx & 15;
            float4 v = *reinterpret_cast<const float4*>(Kg + (size_t)r * D_MODEL + c4 * 4);
            uint32_t off = (uint32_t)(r * 128 + (c4 & 7) * 16);
            sts_tf32x4(Kb + (c4 >> 3) * 8192 + sw128(off), v);
        }
        // V^T tile: [d][key]; lane->key mapping => conflict-free STS
        #pragma unroll
        for (int i = 0; i < 8; i++) {
            int idx = tid + i * 128;
            int key = idx & 63, chunk = idx >> 6;   // chunk 0..15
            float4 v = *reinterpret_cast<const float4*>(Vg + (size_t)key * D_MODEL + chunk * 4);
            uint32_t pan = (uint32_t)((key >> 5) * 8192);
            uint32_t col = (uint32_t)((key & 31) * 4);
            sts_tf32(VTb + pan + sw128((uint32_t)((chunk * 4 + 0) * 128) + col), v.x);
            sts_tf32(VTb + pan + sw128((uint32_t)((chunk * 4 + 1) * 128) + col), v.y);
            sts_tf32(VTb + pan + sw128((uint32_t)((chunk * 4 + 2) * 128) + col), v.z);
            sts_tf32(VTb + pan + sw128((uint32_t)((chunk * 4 + 3) * 128) + col), v.w);
        }
        __syncthreads();

        // ---- scores = Q K^T (16 x 64 per warp) ----
        float sc[8][4];
        #pragma unroll
        for (int nt = 0; nt < 8; nt++)
            #pragma unroll
            for (int e = 0; e < 4; e++) sc[nt][e] = 0.f;

        #pragma unroll
        for (int ks = 0; ks < 8; ks++) {
            uint32_t bf[4][4];
            #pragma unroll
            for (int np = 0; np < 4; np++) {
                uint32_t off = (uint32_t)((np * 16 + b_row) * 128 + ((ks & 3) * 8 + b_col) * 4);
                ldmatrix_x4(bf[np], Kb + (ks >> 2) * 8192 + sw128(off));
            }
            #pragma unroll
            for (int nt = 0; nt < 8; nt++)
                mma_tf32(sc[nt], qf[ks], bf[nt >> 1][(nt & 1) * 2], bf[nt >> 1][(nt & 1) * 2 + 1]);
        }

        // ---- causal mask (diagonal block only) ----
        if (kb == qt) {
            int rg0 = qt * 64 + wid * 16 + r_in;
            int rg1 = rg0 + 8;
            #pragma unroll
            for (int nt = 0; nt < 8; nt++) {
                int cg = kb * 64 + nt * 8 + c2;
                if (cg     > rg0) sc[nt][0] = -INFINITY;
                if (cg + 1 > rg0) sc[nt][1] = -INFINITY;
                if (cg     > rg1) sc[nt][2] = -INFINITY;
                if (cg + 1 > rg1) sc[nt][3] = -INFINITY;
            }
        }

        // ---- online softmax ----
        float mx0 = -INFINITY, mx1 = -INFINITY;
        #pragma unroll
        for (int nt = 0; nt < 8; nt++) {
            mx0 = fmaxf(mx0, fmaxf(sc[nt][0], sc[nt][1]));
            mx1 = fmaxf(mx1, fmaxf(sc[nt][2], sc[nt][3]));
        }
        mx0 = fmaxf(mx0, __shfl_xor_sync(0xffffffffu, mx0, 1));
        mx0 = fmaxf(mx0, __shfl_xor_sync(0xffffffffu, mx0, 2));
        mx1 = fmaxf(mx1, __shfl_xor_sync(0xffffffffu, mx1, 1));
        mx1 = fmaxf(mx1, __shfl_xor_sync(0xffffffffu, mx1, 2));

        float mn0 = fmaxf(m0, mx0), mn1 = fmaxf(m1, mx1);
        float cr0 = __expf(m0 - mn0), cr1 = __expf(m1 - mn1);
        m0 = mn0; m1 = mn1;
        #pragma unroll
        for (int nt = 0; nt < 8; nt++) {
            accv[nt][0] *= cr0; accv[nt][1] *= cr0;
            accv[nt][2] *= cr1; accv[nt][3] *= cr1;
        }
        float s0 = 0.f, s1 = 0.f;
        float p[8][4];
        #pragma unroll
        for (int nt = 0; nt < 8; nt++) {
            p[nt][0] = __expf(sc[nt][0] - mn0);
            p[nt][1] = __expf(sc[nt][1] - mn0);
            p[nt][2] = __expf(sc[nt][2] - mn1);
            p[nt][3] = __expf(sc[nt][3] - mn1);
            s0 += p[nt][0] + p[nt][1];
            s1 += p[nt][2] + p[nt][3];
        }
        s0 += __shfl_xor_sync(0xffffffffu, s0, 1);
        s0 += __shfl_xor_sync(0xffffffffu, s0, 2);
        s1 += __shfl_xor_sync(0xffffffffu, s1, 1);
        s1 += __shfl_xor_sync(0xffffffffu, s1, 2);
        l0 = l0 * cr0 + s0;
        l1 = l1 * cr1 + s1;

        // ---- stage P (tf32) into per-warp smem ----
        #pragma unroll
        for (int nt = 0; nt < 8; nt++) {
            uint32_t pan = (uint32_t)((nt >> 2) * 2048);
            uint32_t colb = (uint32_t)(((nt & 3) * 8 + c2) * 4);
            sts_tf32x2(Pw + pan + sw128((uint32_t)(r_in * 128) + colb),       p[nt][0], p[nt][1]);
            sts_tf32x2(Pw + pan + sw128((uint32_t)((r_in + 8) * 128) + colb), p[nt][2], p[nt][3]);
        }
        __syncwarp();

        // ---- accv += P @ V ----
        #pragma unroll
        for (int ks = 0; ks < 8; ks++) {
            uint32_t pf[4];
            {
                uint32_t off = (uint32_t)(a_row * 128 + ((ks & 3) * 8 + a_col) * 4);
                ldmatrix_x4(pf, Pw + (ks >> 2) * 2048 + sw128(off));
            }
            uint32_t bf[4][4];
            #pragma unroll
            for (int np = 0; np < 4; np++) {
                uint32_t off = (uint32_t)((np * 16 + b_row) * 128 + ((ks & 3) * 8 + b_col) * 4);
                ldmatrix_x4(bf[np], VTb + (ks >> 2) * 8192 + sw128(off));
            }
            #pragma unroll
            for (int nt = 0; nt < 8; nt++)
                mma_tf32(accv[nt], pf, bf[nt >> 1][(nt & 1) * 2], bf[nt >> 1][(nt & 1) * 2 + 1]);
        }
        __syncthreads();
    }

    // ---- finalize: divide by l, write merged[row][h*64+d] ----
    float inv0 = 1.f / l0, inv1 = 1.f / l1;
    int r0 = qt * 64 + wid * 16 + r_in;
    float* Og = O + ((size_t)(b * SEQ)) * D_MODEL + h * D_HEAD;
    #pragma unroll
    for (int nt = 0; nt < 8; nt++) {
        int c0 = nt * 8 + c2;
        float2 v0 = make_float2(accv[nt][0] * inv0, accv[nt][1] * inv0);
        float2 v1 = make_float2(accv[nt][2] * inv1, accv[nt][3] * inv1);
        *reinterpret_cast<float2*>(Og + (size_t)r0 * D_MODEL + c0) = v0;
        *reinterpret_cast<float2*>(Og + (size_t)(r0 + 8) * D_MODEL + c0) = v1;
    }
}

// ---------------- launch ----------------
extern "C" void kernel_launch(void* const* d_in, const int* in_sizes, int n_in,
                              void* d_out, int out_size)
{
    const float* X        = (const float*)d_in[0];
    const float* ln_gamma = (const float*)d_in[1];
    const float* ln_beta  = (const float*)d_in[2];
    const float* Wq       = (const float*)d_in[3];
    const float* bq       = (const float*)d_in[4];
    const float* Wk       = (const float*)d_in[5];
    const float* bk       = (const float*)d_in[6];
    const float* Wv       = (const float*)d_in[7];
    const float* bv       = (const float*)d_in[8];
    const float* Wo       = (const float*)d_in[9];
    const float* bo       = (const float*)d_in[10];
    float* out = (float*)d_out;

    float *Xn, *Qm, *Km, *Vm, *Om;
    cudaGetSymbolAddress((void**)&Xn, g_Xn);
    cudaGetSymbolAddress((void**)&Qm, g_Q);
    cudaGetSymbolAddress((void**)&Km, g_K);
    cudaGetSymbolAddress((void**)&Vm, g_V);
    cudaGetSymbolAddress((void**)&Om, g_O);

    const int gsmem = 4 * GT_STRIDE;   // 64KB
    cudaFuncSetAttribute(gemm_mma, cudaFuncAttributeMaxDynamicSharedMemorySize, gsmem);

    ln_kernel<<<M_ROWS, 256>>>(X, ln_gamma, ln_beta, Xn);

    dim3 ggrid(D_MODEL / 128, M_ROWS / 128);
    gemm_mma<<<ggrid, 256, gsmem>>>(Xn, Wq, bq, Qm);
    gemm_mma<<<ggrid, 256, gsmem>>>(Xn, Wk, bk, Km);
    gemm_mma<<<ggrid, 256, gsmem>>>(Xn, Wv, bv, Vm);

    dim3 agrid(SEQ / 64, N_HEADS, BATCH);
    attn_mma<<<agrid, 128>>>(Qm, Km, Vm, Om);

    gemm_mma<<<ggrid, 256, gsmem>>>(Om, Wo, bo, out);
}

// round 6
// speedup vs baseline: 4.9165x; 1.0490x over previous
#include <cuda_runtime.h>
#include <math.h>
#include <stdint.h>

#define D_MODEL 1024
#define N_HEADS 16
#define D_HEAD  64
#define BATCH   4
#define SEQ     2048
#define M_ROWS  (BATCH * SEQ)   // 8192

// ---------------- helpers ----------------
__device__ __forceinline__ uint32_t smem_u32(const void* p) {
    uint32_t a;
    asm("{ .reg .u64 t; cvta.to.shared.u64 t, %1; cvt.u32.u64 %0, t; }" : "=r"(a) : "l"(p));
    return a;
}
__device__ __forceinline__ uint32_t cvt_tf32(float f) {
    uint32_t o; asm("cvt.rna.tf32.f32 %0, %1;" : "=r"(o) : "f"(f)); return o;
}
__device__ __forceinline__ float tf32f(float f) { return __uint_as_float(cvt_tf32(f)); }
__device__ __forceinline__ void sts_tf32x4(uint32_t addr, float4 v) {
    asm volatile("st.shared.v4.b32 [%0], {%1,%2,%3,%4};" :: "r"(addr),
        "r"(cvt_tf32(v.x)), "r"(cvt_tf32(v.y)), "r"(cvt_tf32(v.z)), "r"(cvt_tf32(v.w)));
}
__device__ __forceinline__ void sts_tf32x2(uint32_t addr, float x, float y) {
    asm volatile("st.shared.v2.b32 [%0], {%1,%2};" :: "r"(addr),
        "r"(cvt_tf32(x)), "r"(cvt_tf32(y)));
}
__device__ __forceinline__ void sts_tf32(uint32_t addr, float x) {
    asm volatile("st.shared.b32 [%0], %1;" :: "r"(addr), "r"(cvt_tf32(x)));
}
__device__ __forceinline__ void ldmatrix_x4(uint32_t* r, uint32_t addr) {
    asm volatile("ldmatrix.sync.aligned.m8n8.x4.shared.b16 {%0,%1,%2,%3}, [%4];"
        : "=r"(r[0]), "=r"(r[1]), "=r"(r[2]), "=r"(r[3]) : "r"(addr));
}
__device__ __forceinline__ void mma_tf32(float* c, const uint32_t* a, uint32_t b0, uint32_t b1) {
    asm volatile("mma.sync.aligned.m16n8k8.row.col.f32.tf32.tf32.f32 "
        "{%0,%1,%2,%3}, {%4,%5,%6,%7}, {%8,%9}, {%0,%1,%2,%3};"
        : "+f"(c[0]), "+f"(c[1]), "+f"(c[2]), "+f"(c[3])
        : "r"(a[0]), "r"(a[1]), "r"(a[2]), "r"(a[3]), "r"(b0), "r"(b1));
}
__device__ __forceinline__ uint32_t sw128(uint32_t off) { return off ^ ((off >> 3) & 0x70); }
__device__ __forceinline__ void cp_async16(uint32_t s, const void* g) {
    asm volatile("cp.async.cg.shared.global [%0], [%1], 16;" :: "r"(s), "l"(g));
}
__device__ __forceinline__ void cp_commit() { asm volatile("cp.async.commit_group;" ::: "memory"); }
template<int N> __device__ __forceinline__ void cp_wait() {
    asm volatile("cp.async.wait_group %0;" :: "n"(N) : "memory");
}

// ---------------- scratch ----------------
__device__ float g_Xn[M_ROWS * D_MODEL];
__device__ float g_Q [M_ROWS * D_MODEL];
__device__ float g_K [M_ROWS * D_MODEL];
__device__ float g_V [M_ROWS * D_MODEL];
__device__ float g_O [M_ROWS * D_MODEL];
__device__ float g_Wc[4 * D_MODEL * D_MODEL];   // tf32-rounded Wq,Wk,Wv,Wo

// ---------------- weight convert (fp32 -> tf32-rounded bits) ----------------
__global__ __launch_bounds__(256) void convert_w(
    const float* __restrict__ Wq, const float* __restrict__ Wk,
    const float* __restrict__ Wv, const float* __restrict__ Wo, float* __restrict__ Wc)
{
    const int NW = D_MODEL * D_MODEL / 4;   // float4s per weight
    int idx = blockIdx.x * 256 + threadIdx.x;
    const float* src[4] = { Wq, Wk, Wv, Wo };
    #pragma unroll
    for (int w = 0; w < 4; w++) {
        float4 v = reinterpret_cast<const float4*>(src[w])[idx];
        v.x = tf32f(v.x); v.y = tf32f(v.y); v.z = tf32f(v.z); v.w = tf32f(v.w);
        reinterpret_cast<float4*>(Wc + (size_t)w * D_MODEL * D_MODEL)[idx] = v;
    }
}

// ---------------- LayerNorm (writes tf32-rounded Xn) ----------------
__global__ __launch_bounds__(256) void ln_kernel(
    const float* __restrict__ X, const float* __restrict__ gamma,
    const float* __restrict__ beta, float* __restrict__ Xn)
{
    int row = blockIdx.x;
    int tid = threadIdx.x;
    const float4* xr = reinterpret_cast<const float4*>(X + (size_t)row * D_MODEL);
    float4 v = xr[tid];

    float s  = v.x + v.y + v.z + v.w;
    float sq = v.x*v.x + v.y*v.y + v.z*v.z + v.w*v.w;

    #pragma unroll
    for (int o = 16; o > 0; o >>= 1) {
        s  += __shfl_xor_sync(0xffffffffu, s,  o);
        sq += __shfl_xor_sync(0xffffffffu, sq, o);
    }
    __shared__ float ss[8], ssq[8];
    int wid = tid >> 5, lid = tid & 31;
    if (lid == 0) { ss[wid] = s; ssq[wid] = sq; }
    __syncthreads();
    if (wid == 0) {
        float a = (lid < 8) ? ss[lid]  : 0.f;
        float b = (lid < 8) ? ssq[lid] : 0.f;
        #pragma unroll
        for (int o = 4; o > 0; o >>= 1) {
            a += __shfl_xor_sync(0xffffffffu, a, o);
            b += __shfl_xor_sync(0xffffffffu, b, o);
        }
        if (lid == 0) { ss[0] = a; ssq[0] = b; }
    }
    __syncthreads();
    float mean = ss[0] * (1.0f / D_MODEL);
    float var  = ssq[0] * (1.0f / D_MODEL) - mean * mean;
    float rstd = rsqrtf(var + 1e-5f);

    const float4* g4 = reinterpret_cast<const float4*>(gamma);
    const float4* b4 = reinterpret_cast<const float4*>(beta);
    float4 gv = g4[tid], bv = b4[tid];
    float4 o;
    o.x = tf32f((v.x - mean) * rstd * gv.x + bv.x);
    o.y = tf32f((v.y - mean) * rstd * gv.y + bv.y);
    o.z = tf32f((v.z - mean) * rstd * gv.z + bv.z);
    o.w = tf32f((v.w - mean) * rstd * gv.w + bv.w);
    reinterpret_cast<float4*>(Xn + (size_t)row * D_MODEL)[tid] = o;
}

// ---------------- tf32 mma.sync GEMM, cp.async 3-stage pipeline ----------------
// A and W must already be tf32-rounded bits. C gets fp32 (+bias).
// grid: (8, 64, nz). blockIdx.z selects weight slab / bias / output.
#define NSTAGE 3
#define STG_BYTES 32768          // A tile 16KB + B tile 16KB

__global__ __launch_bounds__(256, 2) void gemm_mma_async(
    const float* __restrict__ A, const float* __restrict__ Wc, int w_off,
    const float* __restrict__ bias0, const float* __restrict__ bias1, const float* __restrict__ bias2,
    float* __restrict__ C0, float* __restrict__ C1, float* __restrict__ C2)
{
    extern __shared__ char sm[];
    uint32_t sbase = smem_u32(sm);

    const int z = blockIdx.z;
    const float* W = Wc + (size_t)(w_off + z) * D_MODEL * D_MODEL;
    const float* bias = (z == 0) ? bias0 : (z == 1) ? bias1 : bias2;
    float* C = (z == 0) ? C0 : (z == 1) ? C1 : C2;

    const int tid = threadIdx.x;
    const int lane = tid & 31;
    const int wid = tid >> 5;
    const int warp_m = wid >> 2;
    const int warp_n = wid & 3;
    const int bm = blockIdx.y * 128;
    const int bn = blockIdx.x * 128;

    const int Lg = lane >> 3;
    const int Lr = lane & 7;
    const int a_row = ((Lg & 1) << 3) + Lr;
    const int a_col = (Lg >> 1) << 2;
    const int b_row = ((Lg >> 1) << 3) + Lr;
    const int b_col = (Lg & 1) << 2;

    // per-thread fill geometry: 4 chunks of 16B for A, 4 for B
    const int fr = tid >> 1;             // 0..127 row
    const int fj = (tid & 1) << 2;       // 0 or 4 (16B chunk col base)

    float acc[4][4][4];
    #pragma unroll
    for (int mt = 0; mt < 4; mt++)
        #pragma unroll
        for (int nt = 0; nt < 4; nt++)
            #pragma unroll
            for (int e = 0; e < 4; e++) acc[mt][nt][e] = 0.f;

    // issue one stage's loads
    auto issue = [&](int kt, int buf) {
        uint32_t sa = sbase + buf * STG_BYTES;
        uint32_t sb2 = sa + 16384;
        const float* Ag = A + (size_t)(bm + fr) * D_MODEL + kt * 32;
        const float* Wg = W + (size_t)(bn + fr) * D_MODEL + kt * 32;
        #pragma unroll
        for (int q = 0; q < 4; q++) {
            int j = fj + (q & 3);
            // interleave: chunks fj..fj+3 within row fr? need j in 0..7; fj in {0,4}
            uint32_t sw = sw128((uint32_t)(fr * 128 + j * 16));
            cp_async16(sa + sw, Ag + j * 4);
            cp_async16(sb2 + sw, Wg + j * 4);
        }
        cp_commit();
    };

    issue(0, 0);
    issue(1, 1);

    for (int kt = 0; kt < 32; kt++) {
        int buf = kt % NSTAGE;
        cp_wait<1>();
        __syncthreads();
        if (kt + 2 < 32) issue(kt + 2, (kt + 2) % NSTAGE);

        uint32_t abase = sbase + buf * STG_BYTES;
        uint32_t bbase = abase + 16384;

        #pragma unroll
        for (int ks = 0; ks < 4; ks++) {
            uint32_t af[4][4];
            #pragma unroll
            for (int mt = 0; mt < 4; mt++) {
                uint32_t off = (uint32_t)((warp_m * 64 + mt * 16 + a_row) * 128
                                          + (ks * 8 + a_col) * 4);
                ldmatrix_x4(af[mt], abase + sw128(off));
            }
            uint32_t bf[2][4];
            #pragma unroll
            for (int np = 0; np < 2; np++) {
                uint32_t off = (uint32_t)((warp_n * 32 + np * 16 + b_row) * 128
                                          + (ks * 8 + b_col) * 4);
                ldmatrix_x4(bf[np], bbase + sw128(off));
            }
            #pragma unroll
            for (int mt = 0; mt < 4; mt++)
                #pragma unroll
                for (int nt = 0; nt < 4; nt++)
                    mma_tf32(acc[mt][nt], af[mt],
                             bf[nt >> 1][(nt & 1) * 2], bf[nt >> 1][(nt & 1) * 2 + 1]);
        }
        __syncthreads();
    }

    #pragma unroll
    for (int mt = 0; mt < 4; mt++) {
        int r0 = bm + warp_m * 64 + mt * 16 + (lane >> 2);
        #pragma unroll
        for (int nt = 0; nt < 4; nt++) {
            int c0 = bn + warp_n * 32 + nt * 8 + ((lane & 3) << 1);
            float bx = bias[c0], by = bias[c0 + 1];
            float2 v0 = make_float2(acc[mt][nt][0] + bx, acc[mt][nt][1] + by);
            float2 v1 = make_float2(acc[mt][nt][2] + bx, acc[mt][nt][3] + by);
            *reinterpret_cast<float2*>(C + (size_t)r0 * D_MODEL + c0) = v0;
            *reinterpret_cast<float2*>(C + (size_t)(r0 + 8) * D_MODEL + c0) = v1;
        }
    }
}

// ---------------- tf32 mma.sync causal flash attention ----------------
__global__ __launch_bounds__(128) void attn_mma(
    const float* __restrict__ Q, const float* __restrict__ K,
    const float* __restrict__ V, float* __restrict__ O)
{
    __shared__ __align__(1024) char smem_raw[49152];
    uint32_t sb  = smem_u32(smem_raw);
    uint32_t Kb  = sb;            // 16KB
    uint32_t VTb = sb + 16384;    // 16KB
    uint32_t Pb  = sb + 32768;    // 16KB (4KB per warp)

    const int tid = threadIdx.x;
    const int lane = tid & 31;
    const int wid = tid >> 5;
    const int qt = blockIdx.x;
    const int h  = blockIdx.y;
    const int b  = blockIdx.z;

    const int Lg = lane >> 3;
    const int Lr = lane & 7;
    const int a_row = ((Lg & 1) << 3) + Lr;
    const int a_col = (Lg >> 1) << 2;
    const int b_row = ((Lg >> 1) << 3) + Lr;
    const int b_col = (Lg & 1) << 2;

    const int r_in = lane >> 2;
    const int c2   = (lane & 3) << 1;

    const float scale = 0.125f;

    {
        const float* Qg = Q + ((size_t)(b * SEQ + qt * 64)) * D_MODEL + h * D_HEAD;
        #pragma unroll
        for (int i = 0; i < 8; i++) {
            int idx = tid + i * 128;
            int r = idx >> 4, c4 = idx & 15;
            float4 v = *reinterpret_cast<const float4*>(Qg + (size_t)r * D_MODEL + c4 * 4);
            v.x *= scale; v.y *= scale; v.z *= scale; v.w *= scale;
            uint32_t off = (uint32_t)(r * 128 + (c4 & 7) * 16);
            sts_tf32x4(Kb + (c4 >> 3) * 8192 + sw128(off), v);
        }
    }
    __syncthreads();
    uint32_t qf[8][4];
    #pragma unroll
    for (int ks = 0; ks < 8; ks++) {
        uint32_t off = (uint32_t)((wid * 16 + a_row) * 128 + ((ks & 3) * 8 + a_col) * 4);
        ldmatrix_x4(qf[ks], Kb + (ks >> 2) * 8192 + sw128(off));
    }
    __syncthreads();

    float accv[8][4];
    #pragma unroll
    for (int nt = 0; nt < 8; nt++)
        #pragma unroll
        for (int e = 0; e < 4; e++) accv[nt][e] = 0.f;
    float m0 = -INFINITY, m1 = -INFINITY, l0 = 0.f, l1 = 0.f;

    const uint32_t Pw = Pb + wid * 4096;

    for (int kb = 0; kb <= qt; kb++) {
        const float* Kg = K + ((size_t)(b * SEQ + kb * 64)) * D_MODEL + h * D_HEAD;
        const float* Vg = V + ((size_t)(b * SEQ + kb * 64)) * D_MODEL + h * D_HEAD;

        #pragma unroll
        for (int i = 0; i < 8; i++) {
            int idx = tid + i * 128;
            int r = idx >> 4, c4 = idx & 15;
            float4 v = *reinterpret_cast<const float4*>(Kg + (size_t)r * D_MODEL + c4 * 4);
            uint32_t off = (uint32_t)(r * 128 + (c4 & 7) * 16);
            sts_tf32x4(Kb + (c4 >> 3) * 8192 + sw128(off), v);
        }
        #pragma unroll
        for (int i = 0; i < 8; i++) {
            int idx = tid + i * 128;
            int key = idx & 63, chunk = idx >> 6;
            float4 v = *reinterpret_cast<const float4*>(Vg + (size_t)key * D_MODEL + chunk * 4);
            uint32_t pan = (uint32_t)((key >> 5) * 8192);
            uint32_t col = (uint32_t)((key & 31) * 4);
            sts_tf32(VTb + pan + sw128((uint32_t)((chunk * 4 + 0) * 128) + col), v.x);
            sts_tf32(VTb + pan + sw128((uint32_t)((chunk * 4 + 1) * 128) + col), v.y);
            sts_tf32(VTb + pan + sw128((uint32_t)((chunk * 4 + 2) * 128) + col), v.z);
            sts_tf32(VTb + pan + sw128((uint32_t)((chunk * 4 + 3) * 128) + col), v.w);
        }
        __syncthreads();

        float sc[8][4];
        #pragma unroll
        for (int nt = 0; nt < 8; nt++)
            #pragma unroll
            for (int e = 0; e < 4; e++) sc[nt][e] = 0.f;

        #pragma unroll
        for (int ks = 0; ks < 8; ks++) {
            uint32_t bf[4][4];
            #pragma unroll
            for (int np = 0; np < 4; np++) {
                uint32_t off = (uint32_t)((np * 16 + b_row) * 128 + ((ks & 3) * 8 + b_col) * 4);
                ldmatrix_x4(bf[np], Kb + (ks >> 2) * 8192 + sw128(off));
            }
            #pragma unroll
            for (int nt = 0; nt < 8; nt++)
                mma_tf32(sc[nt], qf[ks], bf[nt >> 1][(nt & 1) * 2], bf[nt >> 1][(nt & 1) * 2 + 1]);
        }

        if (kb == qt) {
            int rg0 = qt * 64 + wid * 16 + r_in;
            int rg1 = rg0 + 8;
            #pragma unroll
            for (int nt = 0; nt < 8; nt++) {
                int cg = kb * 64 + nt * 8 + c2;
                if (cg     > rg0) sc[nt][0] = -INFINITY;
                if (cg + 1 > rg0) sc[nt][1] = -INFINITY;
                if (cg     > rg1) sc[nt][2] = -INFINITY;
                if (cg + 1 > rg1) sc[nt][3] = -INFINITY;
            }
        }

        float mx0 = -INFINITY, mx1 = -INFINITY;
        #pragma unroll
        for (int nt = 0; nt < 8; nt++) {
            mx0 = fmaxf(mx0, fmaxf(sc[nt][0], sc[nt][1]));
            mx1 = fmaxf(mx1, fmaxf(sc[nt][2], sc[nt][3]));
        }
        mx0 = fmaxf(mx0, __shfl_xor_sync(0xffffffffu, mx0, 1));
        mx0 = fmaxf(mx0, __shfl_xor_sync(0xffffffffu, mx0, 2));
        mx1 = fmaxf(mx1, __shfl_xor_sync(0xffffffffu, mx1, 1));
        mx1 = fmaxf(mx1, __shfl_xor_sync(0xffffffffu, mx1, 2));

        float mn0 = fmaxf(m0, mx0), mn1 = fmaxf(m1, mx1);
        float cr0 = __expf(m0 - mn0), cr1 = __expf(m1 - mn1);
        m0 = mn0; m1 = mn1;
        #pragma unroll
        for (int nt = 0; nt < 8; nt++) {
            accv[nt][0] *= cr0; accv[nt][1] *= cr0;
            accv[nt][2] *= cr1; accv[nt][3] *= cr1;
        }
        float s0 = 0.f, s1 = 0.f;
        float p[8][4];
        #pragma unroll
        for (int nt = 0; nt < 8; nt++) {
            p[nt][0] = __expf(sc[nt][0] - mn0);
            p[nt][1] = __expf(sc[nt][1] - mn0);
            p[nt][2] = __expf(sc[nt][2] - mn1);
            p[nt][3] = __expf(sc[nt][3] - mn1);
            s0 += p[nt][0] + p[nt][1];
            s1 += p[nt][2] + p[nt][3];
        }
        s0 += __shfl_xor_sync(0xffffffffu, s0, 1);
        s0 += __shfl_xor_sync(0xffffffffu, s0, 2);
        s1 += __shfl_xor_sync(0xffffffffu, s1, 1);
        s1 += __shfl_xor_sync(0xffffffffu, s1, 2);
        l0 = l0 * cr0 + s0;
        l1 = l1 * cr1 + s1;

        #pragma unroll
        for (int nt = 0; nt < 8; nt++) {
            uint32_t pan = (uint32_t)((nt >> 2) * 2048);
            uint32_t colb = (uint32_t)(((nt & 3) * 8 + c2) * 4);
            sts_tf32x2(Pw + pan + sw128((uint32_t)(r_in * 128) + colb),       p[nt][0], p[nt][1]);
            sts_tf32x2(Pw + pan + sw128((uint32_t)((r_in + 8) * 128) + colb), p[nt][2], p[nt][3]);
        }
        __syncwarp();

        #pragma unroll
        for (int ks = 0; ks < 8; ks++) {
            uint32_t pf[4];
            {
                uint32_t off = (uint32_t)(a_row * 128 + ((ks & 3) * 8 + a_col) * 4);
                ldmatrix_x4(pf, Pw + (ks >> 2) * 2048 + sw128(off));
            }
            uint32_t bf[4][4];
            #pragma unroll
            for (int np = 0; np < 4; np++) {
                uint32_t off = (uint32_t)((np * 16 + b_row) * 128 + ((ks & 3) * 8 + b_col) * 4);
                ldmatrix_x4(bf[np], VTb + (ks >> 2) * 8192 + sw128(off));
            }
            #pragma unroll
            for (int nt = 0; nt < 8; nt++)
                mma_tf32(accv[nt], pf, bf[nt >> 1][(nt & 1) * 2], bf[nt >> 1][(nt & 1) * 2 + 1]);
        }
        __syncthreads();
    }

    // finalize (tf32-rounded, feeds Wo GEMM via cp.async)
    float inv0 = 1.f / l0, inv1 = 1.f / l1;
    int r0 = qt * 64 + wid * 16 + r_in;
    float* Og = O + ((size_t)(b * SEQ)) * D_MODEL + h * D_HEAD;
    #pragma unroll
    for (int nt = 0; nt < 8; nt++) {
        int c0 = nt * 8 + c2;
        float2 v0 = make_float2(tf32f(accv[nt][0] * inv0), tf32f(accv[nt][1] * inv0));
        float2 v1 = make_float2(tf32f(accv[nt][2] * inv1), tf32f(accv[nt][3] * inv1));
        *reinterpret_cast<float2*>(Og + (size_t)r0 * D_MODEL + c0) = v0;
        *reinterpret_cast<float2*>(Og + (size_t)(r0 + 8) * D_MODEL + c0) = v1;
    }
}

// ---------------- launch ----------------
extern "C" void kernel_launch(void* const* d_in, const int* in_sizes, int n_in,
                              void* d_out, int out_size)
{
    const float* X        = (const float*)d_in[0];
    const float* ln_gamma = (const float*)d_in[1];
    const float* ln_beta  = (const float*)d_in[2];
    const float* Wq       = (const float*)d_in[3];
    const float* bq       = (const float*)d_in[4];
    const float* Wk       = (const float*)d_in[5];
    const float* bk       = (const float*)d_in[6];
    const float* Wv       = (const float*)d_in[7];
    const float* bv       = (const float*)d_in[8];
    const float* Wo       = (const float*)d_in[9];
    const float* bo       = (const float*)d_in[10];
    float* out = (float*)d_out;

    float *Xn, *Qm, *Km, *Vm, *Om, *Wc;
    cudaGetSymbolAddress((void**)&Xn, g_Xn);
    cudaGetSymbolAddress((void**)&Qm, g_Q);
    cudaGetSymbolAddress((void**)&Km, g_K);
    cudaGetSymbolAddress((void**)&Vm, g_V);
    cudaGetSymbolAddress((void**)&Om, g_O);
    cudaGetSymbolAddress((void**)&Wc, g_Wc);

    const int gsmem = NSTAGE * STG_BYTES;   // 96KB
    cudaFuncSetAttribute(gemm_mma_async, cudaFuncAttributeMaxDynamicSharedMemorySize, gsmem);

    convert_w<<<D_MODEL * D_MODEL / 4 / 256, 256>>>(Wq, Wk, Wv, Wo, Wc);
    ln_kernel<<<M_ROWS, 256>>>(X, ln_gamma, ln_beta, Xn);

    // fused QKV projections
    dim3 qkv_grid(D_MODEL / 128, M_ROWS / 128, 3);
    gemm_mma_async<<<qkv_grid, 256, gsmem>>>(Xn, Wc, 0, bq, bk, bv, Qm, Km, Vm);

    dim3 agrid(SEQ / 64, N_HEADS, BATCH);
    attn_mma<<<agrid, 128>>>(Qm, Km, Vm, Om);

    dim3 o_grid(D_MODEL / 128, M_ROWS / 128, 1);
    gemm_mma_async<<<o_grid, 256, gsmem>>>(Om, Wc, 3, bo, bo, bo, out, out, out);
}

// round 7
// speedup vs baseline: 11.3490x; 2.3083x over previous
#include <cuda_runtime.h>
#include <cuda_fp16.h>
#include <math.h>
#include <stdint.h>

#define D_MODEL 1024
#define N_HEADS 16
#define D_HEAD  64
#define BATCH   4
#define SEQ     2048
#define M_ROWS  (BATCH * SEQ)   // 8192

// ---------------- helpers ----------------
__device__ __forceinline__ uint32_t smem_u32(const void* p) {
    uint32_t a;
    asm("{ .reg .u64 t; cvta.to.shared.u64 t, %1; cvt.u32.u64 %0, t; }" : "=r"(a) : "l"(p));
    return a;
}
__device__ __forceinline__ uint32_t pack_h2(float lo, float hi) {
    uint32_t d; asm("cvt.rn.f16x2.f32 %0, %1, %2;" : "=r"(d) : "f"(hi), "f"(lo)); return d;
}
__device__ __forceinline__ void ldmatrix_x4(uint32_t* r, uint32_t addr) {
    asm volatile("ldmatrix.sync.aligned.m8n8.x4.shared.b16 {%0,%1,%2,%3}, [%4];"
        : "=r"(r[0]), "=r"(r[1]), "=r"(r[2]), "=r"(r[3]) : "r"(addr));
}
__device__ __forceinline__ void ldmatrix_x4_trans(uint32_t* r, uint32_t addr) {
    asm volatile("ldmatrix.sync.aligned.m8n8.x4.trans.shared.b16 {%0,%1,%2,%3}, [%4];"
        : "=r"(r[0]), "=r"(r[1]), "=r"(r[2]), "=r"(r[3]) : "r"(addr));
}
__device__ __forceinline__ void mma_f16(float* c, const uint32_t* a, uint32_t b0, uint32_t b1) {
    asm volatile("mma.sync.aligned.m16n8k16.row.col.f32.f16.f16.f32 "
        "{%0,%1,%2,%3}, {%4,%5,%6,%7}, {%8,%9}, {%0,%1,%2,%3};"
        : "+f"(c[0]), "+f"(c[1]), "+f"(c[2]), "+f"(c[3])
        : "r"(a[0]), "r"(a[1]), "r"(a[2]), "r"(a[3]), "r"(b0), "r"(b1));
}
__device__ __forceinline__ uint32_t sw128(uint32_t off) { return off ^ ((off >> 3) & 0x70); }
__device__ __forceinline__ void cp_async16(uint32_t s, const void* g) {
    asm volatile("cp.async.cg.shared.global [%0], [%1], 16;" :: "r"(s), "l"(g));
}
__device__ __forceinline__ void cp_commit() { asm volatile("cp.async.commit_group;" ::: "memory"); }
template<int N> __device__ __forceinline__ void cp_wait() {
    asm volatile("cp.async.wait_group %0;" :: "n"(N) : "memory");
}

// ---------------- scratch (half precision working set) ----------------
__device__ __half g_Xn[M_ROWS * D_MODEL];
__device__ __half g_Q [M_ROWS * D_MODEL];
__device__ __half g_K [M_ROWS * D_MODEL];
__device__ __half g_V [M_ROWS * D_MODEL];
__device__ __half g_O [M_ROWS * D_MODEL];
__device__ __half g_Wh[4 * D_MODEL * D_MODEL];   // Wq,Wk,Wv,Wo as fp16

// ---------------- weight convert (fp32 -> fp16) ----------------
__global__ __launch_bounds__(256) void convert_w(
    const float* __restrict__ Wq, const float* __restrict__ Wk,
    const float* __restrict__ Wv, const float* __restrict__ Wo, __half* __restrict__ Wh)
{
    int idx = blockIdx.x * 256 + threadIdx.x;
    const float* src[4] = { Wq, Wk, Wv, Wo };
    #pragma unroll
    for (int w = 0; w < 4; w++) {
        float4 v = reinterpret_cast<const float4*>(src[w])[idx];
        uint2 o;
        o.x = pack_h2(v.x, v.y);
        o.y = pack_h2(v.z, v.w);
        reinterpret_cast<uint2*>(Wh + (size_t)w * D_MODEL * D_MODEL)[idx] = o;
    }
}

// ---------------- LayerNorm (fp32 in, fp16 out) ----------------
__global__ __launch_bounds__(256) void ln_kernel(
    const float* __restrict__ X, const float* __restrict__ gamma,
    const float* __restrict__ beta, __half* __restrict__ Xn)
{
    int row = blockIdx.x;
    int tid = threadIdx.x;
    const float4* xr = reinterpret_cast<const float4*>(X + (size_t)row * D_MODEL);
    float4 v = xr[tid];

    float s  = v.x + v.y + v.z + v.w;
    float sq = v.x*v.x + v.y*v.y + v.z*v.z + v.w*v.w;

    #pragma unroll
    for (int o = 16; o > 0; o >>= 1) {
        s  += __shfl_xor_sync(0xffffffffu, s,  o);
        sq += __shfl_xor_sync(0xffffffffu, sq, o);
    }
    __shared__ float ss[8], ssq[8];
    int wid = tid >> 5, lid = tid & 31;
    if (lid == 0) { ss[wid] = s; ssq[wid] = sq; }
    __syncthreads();
    if (wid == 0) {
        float a = (lid < 8) ? ss[lid]  : 0.f;
        float bb = (lid < 8) ? ssq[lid] : 0.f;
        #pragma unroll
        for (int o = 4; o > 0; o >>= 1) {
            a  += __shfl_xor_sync(0xffffffffu, a, o);
            bb += __shfl_xor_sync(0xffffffffu, bb, o);
        }
        if (lid == 0) { ss[0] = a; ssq[0] = bb; }
    }
    __syncthreads();
    float mean = ss[0] * (1.0f / D_MODEL);
    float var  = ssq[0] * (1.0f / D_MODEL) - mean * mean;
    float rstd = rsqrtf(var + 1e-5f);

    const float4* g4 = reinterpret_cast<const float4*>(gamma);
    const float4* b4 = reinterpret_cast<const float4*>(beta);
    float4 gv = g4[tid], bv = b4[tid];
    uint2 o;
    o.x = pack_h2((v.x - mean) * rstd * gv.x + bv.x, (v.y - mean) * rstd * gv.y + bv.y);
    o.y = pack_h2((v.z - mean) * rstd * gv.z + bv.z, (v.w - mean) * rstd * gv.w + bv.w);
    reinterpret_cast<uint2*>(Xn + (size_t)row * D_MODEL)[tid] = o;
}

// ---------------- fp16 mma GEMM: C = A @ W^T + bias ----------------
// CTA 128x128, BK=64, 3-stage cp.async, 256 threads (2m x 4n warps of 64x32).
#define GSTG 32768   // stage = A tile 16KB + B tile 16KB

__global__ __launch_bounds__(256, 2) void gemm_h(
    const __half* __restrict__ A, const __half* __restrict__ Wh, int w_off,
    const float* __restrict__ bias0, const float* __restrict__ bias1, const float* __restrict__ bias2,
    void* __restrict__ C0, void* __restrict__ C1, void* __restrict__ C2, int half_out)
{
    extern __shared__ char sm[];
    uint32_t sbase = smem_u32(sm);

    const int z = blockIdx.z;
    const __half* W = Wh + (size_t)(w_off + z) * D_MODEL * D_MODEL;
    const float* bias = (z == 0) ? bias0 : (z == 1) ? bias1 : bias2;
    void* C = (z == 0) ? C0 : (z == 1) ? C1 : C2;

    const int tid = threadIdx.x;
    const int lane = tid & 31;
    const int wid = tid >> 5;
    const int warp_m = wid >> 2;
    const int warp_n = wid & 3;
    const int bm = blockIdx.y * 128;
    const int bn = blockIdx.x * 128;

    const int Lg = lane >> 3;
    const int Lr = lane & 7;
    const int a_row = ((Lg & 1) << 3) + Lr;       // A frag row
    const int a_byte = (Lg >> 1) << 4;            // A frag k-byte (0/16)
    const int b_row = Lr + ((Lg >> 1) << 3);      // B frag n-row
    const int b_byte = (Lg & 1) << 4;             // B frag k-byte

    // fill geometry: 128 rows x 8 chunks(16B) per tile; 4 chunks/thread/tile
    const int fr = tid >> 1;
    const int fj = (tid & 1) << 2;

    float acc[4][4][4];
    #pragma unroll
    for (int mt = 0; mt < 4; mt++)
        #pragma unroll
        for (int nt = 0; nt < 4; nt++)
            #pragma unroll
            for (int e = 0; e < 4; e++) acc[mt][nt][e] = 0.f;

    auto issue = [&](int kt) {
        uint32_t sa = sbase + (kt % 3) * GSTG;
        uint32_t sb2 = sa + 16384;
        const __half* Ag = A + (size_t)(bm + fr) * D_MODEL + kt * 64;
        const __half* Wg = W + (size_t)(bn + fr) * D_MODEL + kt * 64;
        #pragma unroll
        for (int q = 0; q < 4; q++) {
            int j = fj + q;
            uint32_t sw = sw128((uint32_t)(fr * 128 + j * 16));
            cp_async16(sa + sw, Ag + j * 8);
            cp_async16(sb2 + sw, Wg + j * 8);
        }
        cp_commit();
    };

    issue(0);
    issue(1);

    for (int kt = 0; kt < 16; kt++) {
        if (kt < 15) cp_wait<1>(); else cp_wait<0>();
        __syncthreads();
        if (kt + 2 < 16) issue(kt + 2);

        uint32_t abase = sbase + (kt % 3) * GSTG;
        uint32_t bbase = abase + 16384;

        #pragma unroll
        for (int ks = 0; ks < 4; ks++) {
            uint32_t af[4][4];
            #pragma unroll
            for (int mt = 0; mt < 4; mt++)
                ldmatrix_x4(af[mt], abase + sw128(
                    (uint32_t)((warp_m * 64 + mt * 16 + a_row) * 128 + ks * 32 + a_byte)));
            uint32_t bfr[2][4];
            #pragma unroll
            for (int np = 0; np < 2; np++)
                ldmatrix_x4(bfr[np], bbase + sw128(
                    (uint32_t)((warp_n * 32 + np * 16 + b_row) * 128 + ks * 32 + b_byte)));
            #pragma unroll
            for (int mt = 0; mt < 4; mt++)
                #pragma unroll
                for (int nt = 0; nt < 4; nt++)
                    mma_f16(acc[mt][nt], af[mt],
                            bfr[nt >> 1][(nt & 1) * 2], bfr[nt >> 1][(nt & 1) * 2 + 1]);
        }
        __syncthreads();
    }

    const int r_in = lane >> 2;
    const int c2 = (lane & 3) << 1;
    #pragma unroll
    for (int mt = 0; mt < 4; mt++) {
        int r0 = bm + warp_m * 64 + mt * 16 + r_in;
        #pragma unroll
        for (int nt = 0; nt < 4; nt++) {
            int c0 = bn + warp_n * 32 + nt * 8 + c2;
            float bx = bias[c0], by = bias[c0 + 1];
            float v00 = acc[mt][nt][0] + bx, v01 = acc[mt][nt][1] + by;
            float v10 = acc[mt][nt][2] + bx, v11 = acc[mt][nt][3] + by;
            if (half_out) {
                uint32_t* Ch = (uint32_t*)C;
                Ch[((size_t)r0 * D_MODEL + c0) >> 1]       = pack_h2(v00, v01);
                Ch[((size_t)(r0 + 8) * D_MODEL + c0) >> 1] = pack_h2(v10, v11);
            } else {
                float* Cf = (float*)C;
                *reinterpret_cast<float2*>(Cf + (size_t)r0 * D_MODEL + c0) = make_float2(v00, v01);
                *reinterpret_cast<float2*>(Cf + (size_t)(r0 + 8) * D_MODEL + c0) = make_float2(v10, v11);
            }
        }
    }
}

// ---------------- fp16 mma causal flash attention ----------------
// CTA: 64 queries of one (b,h), 4 warps x 16 rows, 64-key blocks,
// double-buffered cp.async K/V tiles, P held in registers (C->A frag identity).
__global__ __launch_bounds__(128) void attn_h(
    const __half* __restrict__ Q, const __half* __restrict__ K,
    const __half* __restrict__ V, __half* __restrict__ O)
{
    __shared__ __align__(1024) char smem_raw[40960];
    uint32_t sb = smem_u32(smem_raw);
    const uint32_t Qs = sb;                     // 8KB: 64q x 128B
    // stages: K at sb+8192+s*16384, V at +8192 more

    const int tid = threadIdx.x;
    const int lane = tid & 31;
    const int wid = tid >> 5;
    const int qt = blockIdx.x;
    const int h  = blockIdx.y;
    const int b  = blockIdx.z;

    const int Lg = lane >> 3;
    const int Lr = lane & 7;
    const int a_row = ((Lg & 1) << 3) + Lr;
    const int a_byte = (Lg >> 1) << 4;
    const int k_row = Lr + ((Lg >> 1) << 3);    // K frag (B, n=key)
    const int k_byte = (Lg & 1) << 4;
    const int v_row = Lr + ((Lg & 1) << 3);     // V frag (B-trans, rows=key)
    const int v_byte = (Lg >> 1) << 4;

    const int r_in = lane >> 2;
    const int c2 = (lane & 3) << 1;

    const float scale = 0.125f;

    const __half* Qg = Q + ((size_t)(b * SEQ + qt * 64)) * D_MODEL + h * D_HEAD;

    // prologue: Q tile + KV block 0 via cp.async
    {
        #pragma unroll
        for (int i = 0; i < 4; i++) {
            int slot = tid + i * 128;
            int r = slot >> 3, j = slot & 7;
            cp_async16(Qs + sw128((uint32_t)(r * 128 + j * 16)), Qg + r * D_MODEL + j * 8);
        }
        cp_commit();
    }
    auto issue_kv = [&](int kb) {
        uint32_t Kst = sb + 8192 + (kb & 1) * 16384;
        uint32_t Vst = Kst + 8192;
        const __half* Kg = K + ((size_t)(b * SEQ + kb * 64)) * D_MODEL + h * D_HEAD;
        const __half* Vg = V + ((size_t)(b * SEQ + kb * 64)) * D_MODEL + h * D_HEAD;
        #pragma unroll
        for (int i = 0; i < 4; i++) {
            int slot = tid + i * 128;
            int r = slot >> 3, j = slot & 7;
            uint32_t sw = sw128((uint32_t)(r * 128 + j * 16));
            cp_async16(Kst + sw, Kg + r * D_MODEL + j * 8);
            cp_async16(Vst + sw, Vg + r * D_MODEL + j * 8);
        }
        cp_commit();
    };
    issue_kv(0);

    cp_wait<1>();   // Q arrived
    __syncthreads();

    uint32_t qf[4][4];
    #pragma unroll
    for (int ks = 0; ks < 4; ks++)
        ldmatrix_x4(qf[ks], Qs + sw128(
            (uint32_t)((wid * 16 + a_row) * 128 + ks * 32 + a_byte)));

    float accv[8][4];
    #pragma unroll
    for (int nt = 0; nt < 8; nt++)
        #pragma unroll
        for (int e = 0; e < 4; e++) accv[nt][e] = 0.f;
    float m0 = -INFINITY, m1 = -INFINITY, l0 = 0.f, l1 = 0.f;

    for (int kb = 0; kb <= qt; kb++) {
        cp_wait<0>();
        __syncthreads();
        if (kb < qt) issue_kv(kb + 1);

        uint32_t Kst = sb + 8192 + (kb & 1) * 16384;
        uint32_t Vst = Kst + 8192;

        // ---- scores = Q K^T ----
        float sc[8][4];
        #pragma unroll
        for (int nt = 0; nt < 8; nt++)
            #pragma unroll
            for (int e = 0; e < 4; e++) sc[nt][e] = 0.f;

        #pragma unroll
        for (int ks = 0; ks < 4; ks++) {
            #pragma unroll
            for (int kp = 0; kp < 4; kp++) {
                uint32_t kf[4];
                ldmatrix_x4(kf, Kst + sw128(
                    (uint32_t)((kp * 16 + k_row) * 128 + ks * 32 + k_byte)));
                mma_f16(sc[kp * 2],     qf[ks], kf[0], kf[1]);
                mma_f16(sc[kp * 2 + 1], qf[ks], kf[2], kf[3]);
            }
        }

        // scale + causal mask (diagonal block only)
        #pragma unroll
        for (int nt = 0; nt < 8; nt++) {
            sc[nt][0] *= scale; sc[nt][1] *= scale;
            sc[nt][2] *= scale; sc[nt][3] *= scale;
        }
        if (kb == qt) {
            int rg0 = qt * 64 + wid * 16 + r_in;
            int rg1 = rg0 + 8;
            #pragma unroll
            for (int nt = 0; nt < 8; nt++) {
                int cg = kb * 64 + nt * 8 + c2;
                if (cg     > rg0) sc[nt][0] = -INFINITY;
                if (cg + 1 > rg0) sc[nt][1] = -INFINITY;
                if (cg     > rg1) sc[nt][2] = -INFINITY;
                if (cg + 1 > rg1) sc[nt][3] = -INFINITY;
            }
        }

        // ---- online softmax ----
        float mx0 = -INFINITY, mx1 = -INFINITY;
        #pragma unroll
        for (int nt = 0; nt < 8; nt++) {
            mx0 = fmaxf(mx0, fmaxf(sc[nt][0], sc[nt][1]));
            mx1 = fmaxf(mx1, fmaxf(sc[nt][2], sc[nt][3]));
        }
        mx0 = fmaxf(mx0, __shfl_xor_sync(0xffffffffu, mx0, 1));
        mx0 = fmaxf(mx0, __shfl_xor_sync(0xffffffffu, mx0, 2));
        mx1 = fmaxf(mx1, __shfl_xor_sync(0xffffffffu, mx1, 1));
        mx1 = fmaxf(mx1, __shfl_xor_sync(0xffffffffu, mx1, 2));

        float mn0 = fmaxf(m0, mx0), mn1 = fmaxf(m1, mx1);
        float cr0 = __expf(m0 - mn0), cr1 = __expf(m1 - mn1);
        m0 = mn0; m1 = mn1;
        #pragma unroll
        for (int nt = 0; nt < 8; nt++) {
            accv[nt][0] *= cr0; accv[nt][1] *= cr0;
            accv[nt][2] *= cr1; accv[nt][3] *= cr1;
        }
        float s0 = 0.f, s1 = 0.f;
        #pragma unroll
        for (int nt = 0; nt < 8; nt++) {
            sc[nt][0] = __expf(sc[nt][0] - mn0);
            sc[nt][1] = __expf(sc[nt][1] - mn0);
            sc[nt][2] = __expf(sc[nt][2] - mn1);
            sc[nt][3] = __expf(sc[nt][3] - mn1);
            s0 += sc[nt][0] + sc[nt][1];
            s1 += sc[nt][2] + sc[nt][3];
        }
        s0 += __shfl_xor_sync(0xffffffffu, s0, 1);
        s0 += __shfl_xor_sync(0xffffffffu, s0, 2);
        s1 += __shfl_xor_sync(0xffffffffu, s1, 1);
        s1 += __shfl_xor_sync(0xffffffffu, s1, 2);
        l0 = l0 * cr0 + s0;
        l1 = l1 * cr1 + s1;

        // ---- accv += P @ V  (P: C-frag -> A-frag, pure register pack) ----
        #pragma unroll
        for (int ks2 = 0; ks2 < 4; ks2++) {
            uint32_t pf[4];
            pf[0] = pack_h2(sc[2*ks2][0],     sc[2*ks2][1]);
            pf[1] = pack_h2(sc[2*ks2][2],     sc[2*ks2][3]);
            pf[2] = pack_h2(sc[2*ks2 + 1][0], sc[2*ks2 + 1][1]);
            pf[3] = pack_h2(sc[2*ks2 + 1][2], sc[2*ks2 + 1][3]);
            #pragma unroll
            for (int dn = 0; dn < 4; dn++) {
                uint32_t vf[4];
                ldmatrix_x4_trans(vf, Vst + sw128(
                    (uint32_t)((ks2 * 16 + v_row) * 128 + dn * 32 + v_byte)));
                mma_f16(accv[dn * 2],     pf, vf[0], vf[1]);
                mma_f16(accv[dn * 2 + 1], pf, vf[2], vf[3]);
            }
        }
    }

    // ---- finalize: /l, fp16 out ----
    float inv0 = 1.f / l0, inv1 = 1.f / l1;
    int r0 = qt * 64 + wid * 16 + r_in;
    uint32_t* Og = (uint32_t*)(O + ((size_t)(b * SEQ)) * D_MODEL + h * D_HEAD);
    #pragma unroll
    for (int nt = 0; nt < 8; nt++) {
        int c0 = nt * 8 + c2;
        Og[((size_t)r0 * D_MODEL + c0) >> 1]       = pack_h2(accv[nt][0] * inv0, accv[nt][1] * inv0);
        Og[((size_t)(r0 + 8) * D_MODEL + c0) >> 1] = pack_h2(accv[nt][2] * inv1, accv[nt][3] * inv1);
    }
}

// ---------------- launch ----------------
extern "C" void kernel_launch(void* const* d_in, const int* in_sizes, int n_in,
                              void* d_out, int out_size)
{
    const float* X        = (const float*)d_in[0];
    const float* ln_gamma = (const float*)d_in[1];
    const float* ln_beta  = (const float*)d_in[2];
    const float* Wq       = (const float*)d_in[3];
    const float* bq       = (const float*)d_in[4];
    const float* Wk       = (const float*)d_in[5];
    const float* bk       = (const float*)d_in[6];
    const float* Wv       = (const float*)d_in[7];
    const float* bv       = (const float*)d_in[8];
    const float* Wo       = (const float*)d_in[9];
    const float* bo       = (const float*)d_in[10];
    float* out = (float*)d_out;

    __half *Xn, *Qm, *Km, *Vm, *Om, *Wh;
    cudaGetSymbolAddress((void**)&Xn, g_Xn);
    cudaGetSymbolAddress((void**)&Qm, g_Q);
    cudaGetSymbolAddress((void**)&Km, g_K);
    cudaGetSymbolAddress((void**)&Vm, g_V);
    cudaGetSymbolAddress((void**)&Om, g_O);
    cudaGetSymbolAddress((void**)&Wh, g_Wh);

    const int gsmem = 3 * GSTG;   // 96KB
    cudaFuncSetAttribute(gemm_h, cudaFuncAttributeMaxDynamicSharedMemorySize, gsmem);

    convert_w<<<D_MODEL * D_MODEL / 4 / 256, 256>>>(Wq, Wk, Wv, Wo, Wh);
    ln_kernel<<<M_ROWS, 256>>>(X, ln_gamma, ln_beta, Xn);

    dim3 qkv_grid(D_MODEL / 128, M_ROWS / 128, 3);
    gemm_h<<<qkv_grid, 256, gsmem>>>(Xn, Wh, 0, bq, bk, bv, Qm, Km, Vm, 1);

    dim3 agrid(SEQ / 64, N_HEADS, BATCH);
    attn_h<<<agrid, 128>>>(Qm, Km, Vm, Om);

    dim3 o_grid(D_MODEL / 128, M_ROWS / 128, 1);
    gemm_h<<<o_grid, 256, gsmem>>>(Om, Wh, 3, bo, bo, bo, out, out, out, 0);
}